// round 2
// baseline (speedup 1.0000x reference)
#include <cuda_runtime.h>
#include <math.h>
#include <stdint.h>

#define B_ 8
#define C_ 1024
#define T_ 2048
#define I_ 512
#define BN_EPS 1e-5f

typedef unsigned long long u64;

// ---------------- static scratch (allocation-free) ----------------
__device__ float g_pg[B_ * I_ * T_];                 // g projection   [B,I,T]
__device__ float g_pt[B_ * I_ * T_];                 // theta proj     [B,I,T]
__device__ float g_pp[B_ * I_ * T_];                 // phi proj       [B,I,T]
__device__ float g_at[(long long)B_ * T_ * T_];      // scores^T / exp [B,S,T]
__device__ float g_yv[B_ * I_ * T_];                 // y' (unnormalized) [B,I,T]
__device__ float g_z[B_ * T_];                       // 1/Z per (b,t)
__device__ float g_mean[C_];
__device__ float g_rstd[C_];

// ---------------- packed-f32x2 GEMM ----------------
#define BM 128
#define BN 128
#define BK 8

#define FMA2(d, a, b) asm("fma.rn.f32x2 %0, %1, %2, %0;" : "+l"(d) : "l"(a), "l"(b))
#define LDSV2(x, y, addr) \
    asm volatile("ld.shared.v2.u64 {%0, %1}, [%2];" : "=l"(x), "=l"(y) : "r"(addr))

__device__ __forceinline__ float lo32(u64 v) { return __uint_as_float((unsigned)v); }
__device__ __forceinline__ float hi32(u64 v) { return __uint_as_float((unsigned)(v >> 32)); }

// C[z] = op(A[z]) * B[z]  (+ epilogue)
// TA=false: A[m*lda+k] (weights, row-major, k contiguous)
// TA=true : A[k*lda+m] (activation, m contiguous)
// B always B[k*ldb+n] (n contiguous)
// EPI bitmask: 1=+bias[m], 2=+resid, 4=*colscale[n]
template <bool TA, int EPI>
__global__ __launch_bounds__(256, 2)
void gemm_f32x2(const float* __restrict__ A, const float* __restrict__ Bm,
                float* __restrict__ Cm,
                const float* __restrict__ bias, const float* __restrict__ resid,
                const float* __restrict__ zscale,
                int K, int lda, int ldb, int ldc,
                long long sA, long long sB, long long sC, long long sR, long long sZ)
{
    __shared__ float As[2][BK][BM];         // 8 KB
    __shared__ float Bsd[2][BK][2 * BN];    // 16 KB (column-duplicated)

    const int tid = threadIdx.x;
    const int bm0 = blockIdx.y * BM;
    const int bn0 = blockIdx.x * BN;

    A  += sA * blockIdx.z;
    Bm += sB * blockIdx.z;
    Cm += sC * blockIdx.z;

    const int tr = tid >> 4;   // 0..15 row group
    const int tc = tid & 15;   // 0..15 col group

    u64 acc[4][8];
#pragma unroll
    for (int i = 0; i < 4; i++)
#pragma unroll
        for (int j = 0; j < 8; j++) acc[i][j] = 0ull;

    const uint32_t as_base = (uint32_t)__cvta_generic_to_shared(&As[0][0][0]);
    const uint32_t bs_base = (uint32_t)__cvta_generic_to_shared(&Bsd[0][0][0]);

    // ---- tile loaders (global -> regs -> smem) ----
    float4 ra, rb;
    auto load_tile = [&](int k0) {
        if (TA) {
            int k = tid >> 5, mg = (tid & 31) << 2;
            ra = *(const float4*)&A[(long long)(k0 + k) * lda + bm0 + mg];
        } else {
            int m = tid >> 1, kg = (tid & 1) << 2;
            ra = *(const float4*)&A[(long long)(bm0 + m) * lda + k0 + kg];
        }
        int kb = tid >> 5, ng = (tid & 31) << 2;
        rb = *(const float4*)&Bm[(long long)(k0 + kb) * ldb + bn0 + ng];
    };
    auto store_tile = [&](int buf) {
        if (TA) {
            int k = tid >> 5, mg = (tid & 31) << 2;
            *(float4*)&As[buf][k][mg] = ra;
        } else {
            int m = tid >> 1, kg = (tid & 1) << 2;
            As[buf][kg + 0][m] = ra.x;
            As[buf][kg + 1][m] = ra.y;
            As[buf][kg + 2][m] = ra.z;
            As[buf][kg + 3][m] = ra.w;
        }
        int kb = tid >> 5, ng = (tid & 31) << 2;
        *(float4*)&Bsd[buf][kb][2 * ng]     = make_float4(rb.x, rb.x, rb.y, rb.y);
        *(float4*)&Bsd[buf][kb][2 * ng + 4] = make_float4(rb.z, rb.z, rb.w, rb.w);
    };

    // prologue
    load_tile(0);
    store_tile(0);
    __syncthreads();

    const int ntiles = K / BK;
    int buf = 0;
    for (int t = 0; t < ntiles; t++) {
        const bool has_next = (t + 1 < ntiles);
        if (has_next) load_tile((t + 1) * BK);

        const uint32_t a_tile = as_base + buf * (BK * BM * 4);
        const uint32_t b_tile = bs_base + buf * (BK * 2 * BN * 4);
#pragma unroll
        for (int k = 0; k < BK; k++) {
            u64 a2[4], bb[8];
            uint32_t aa = a_tile + (k * BM + tr * 4) * 4;
            LDSV2(a2[0], a2[1], aa);
            LDSV2(a2[2], a2[3], aa + 256);           // +64 rows
            uint32_t ba = b_tile + k * (2 * BN * 4) + tc * 32;
            LDSV2(bb[0], bb[1], ba);
            LDSV2(bb[2], bb[3], ba + 16);
            LDSV2(bb[4], bb[5], ba + 512);           // +64 cols (dup)
            LDSV2(bb[6], bb[7], ba + 528);
#pragma unroll
            for (int rp = 0; rp < 4; rp++)
#pragma unroll
                for (int j = 0; j < 8; j++)
                    FMA2(acc[rp][j], a2[rp], bb[j]);
        }

        if (has_next) store_tile(buf ^ 1);
        __syncthreads();
        buf ^= 1;
    }

    // ---- epilogue ----
    const float* zrow = (EPI & 4) ? (zscale + sZ * blockIdx.z) : nullptr;
    const float* rbase = (EPI & 2) ? (resid + sR * blockIdx.z) : nullptr;
    const int n0 = bn0 + tc * 4;
    const int n1 = n0 + 64;
#pragma unroll
    for (int rp = 0; rp < 4; rp++) {
        const int mrel = ((rp >> 1) ? 64 : 0) + tr * 4 + (rp & 1) * 2;
#pragma unroll
        for (int h = 0; h < 2; h++) {
            const int m = bm0 + mrel + h;
            const long long rowoff = (long long)m * ldc;
            float v[8];
#pragma unroll
            for (int j = 0; j < 8; j++)
                v[j] = h ? hi32(acc[rp][j]) : lo32(acc[rp][j]);
            if (EPI & 4) {
#pragma unroll
                for (int j = 0; j < 4; j++) { v[j] *= zrow[n0 + j]; v[4 + j] *= zrow[n1 + j]; }
            }
            if (EPI & 1) {
                const float bv = bias[m];
#pragma unroll
                for (int j = 0; j < 8; j++) v[j] += bv;
            }
            if (EPI & 2) {
#pragma unroll
                for (int j = 0; j < 4; j++) {
                    v[j]     += rbase[rowoff + n0 + j];
                    v[4 + j] += rbase[rowoff + n1 + j];
                }
            }
            *(float4*)&Cm[rowoff + n0] = make_float4(v[0], v[1], v[2], v[3]);
            *(float4*)&Cm[rowoff + n1] = make_float4(v[4], v[5], v[6], v[7]);
        }
    }
}

// ---------------- column softmax (over s) on fT[b][s][t]; stores exp, invZ ----
__global__ __launch_bounds__(256)
void softmax_cols(float* __restrict__ f, float* __restrict__ invZ)
{
    const int b = blockIdx.y;
    const int t = blockIdx.x * 32 + threadIdx.x;
    const int ty = threadIdx.y;  // 0..7
    float* fb = f + (long long)b * T_ * T_;

    float mx = -1e30f;
#pragma unroll 8
    for (int s = ty; s < T_; s += 8)
        mx = fmaxf(mx, fb[(long long)s * T_ + t]);

    __shared__ float red1[8][32];
    __shared__ float red2[8][32];
    red1[ty][threadIdx.x] = mx;
    __syncthreads();
#pragma unroll
    for (int i = 0; i < 8; i++) mx = fmaxf(mx, red1[i][threadIdx.x]);

    float sum = 0.0f;
#pragma unroll 8
    for (int s = ty; s < T_; s += 8) {
        const long long idx = (long long)s * T_ + t;
        const float v = __expf(fb[idx] - mx);
        fb[idx] = v;
        sum += v;
    }
    red2[ty][threadIdx.x] = sum;
    __syncthreads();
    if (ty == 0) {
        float tot = 0.0f;
#pragma unroll
        for (int i = 0; i < 8; i++) tot += red2[i][threadIdx.x];
        invZ[(long long)b * T_ + t] = 1.0f / tot;
    }
}

// ---------------- batchnorm ----------------
__global__ __launch_bounds__(256)
void bn_stats(const float* __restrict__ s, float* __restrict__ mean,
              float* __restrict__ rstd)
{
    const int c = blockIdx.x;
    const int tid = threadIdx.x;
    float sum = 0.0f, sq = 0.0f;
    for (int idx = tid; idx < B_ * T_; idx += 256) {
        int b = idx >> 11;
        int t = idx & (T_ - 1);
        float v = s[(long long)b * C_ * T_ + (long long)c * T_ + t];
        sum += v;
        sq = fmaf(v, v, sq);
    }
    __shared__ float r1[256], r2[256];
    r1[tid] = sum; r2[tid] = sq;
    __syncthreads();
#pragma unroll
    for (int st = 128; st > 0; st >>= 1) {
        if (tid < st) { r1[tid] += r1[tid + st]; r2[tid] += r2[tid + st]; }
        __syncthreads();
    }
    if (tid == 0) {
        const float inv_n = 1.0f / (float)(B_ * T_);
        float m = r1[0] * inv_n;
        float var = r2[0] * inv_n - m * m;
        mean[c] = m;
        rstd[c] = rsqrtf(var + BN_EPS);
    }
}

__global__ __launch_bounds__(256)
void bn_apply(float* __restrict__ s, const float* __restrict__ mean,
              const float* __restrict__ rstd, const float* __restrict__ gamma,
              const float* __restrict__ beta)
{
    const int bc = blockIdx.x;
    const int c = bc & (C_ - 1);
    const long long base = (long long)bc * T_;
    const float m = mean[c], r = rstd[c], g = gamma[c], be = beta[c];
    for (int t = threadIdx.x; t < T_; t += 256)
        s[base + t] = fmaf((s[base + t] - m) * r, g, be);
}

// ---------------- launcher ----------------
extern "C" void kernel_launch(void* const* d_in, const int* in_sizes, int n_in,
                              void* d_out, int out_size)
{
    const float* x     = (const float*)d_in[0];
    const float* g_w   = (const float*)d_in[1];
    const float* g_b   = (const float*)d_in[2];
    const float* th_w  = (const float*)d_in[3];
    const float* th_b  = (const float*)d_in[4];
    const float* ph_w  = (const float*)d_in[5];
    const float* ph_b  = (const float*)d_in[6];
    const float* W_w   = (const float*)d_in[7];
    const float* W_b   = (const float*)d_in[8];
    const float* gamma = (const float*)d_in[9];
    const float* beta  = (const float*)d_in[10];
    float* out = (float*)d_out;

    float *pg, *pt, *pp, *at, *yv, *iz, *mean, *rstd;
    cudaGetSymbolAddress((void**)&pg, g_pg);
    cudaGetSymbolAddress((void**)&pt, g_pt);
    cudaGetSymbolAddress((void**)&pp, g_pp);
    cudaGetSymbolAddress((void**)&at, g_at);
    cudaGetSymbolAddress((void**)&yv, g_yv);
    cudaGetSymbolAddress((void**)&iz, g_z);
    cudaGetSymbolAddress((void**)&mean, g_mean);
    cudaGetSymbolAddress((void**)&rstd, g_rstd);

    const long long sX = (long long)C_ * T_;
    const long long sP = (long long)I_ * T_;
    const long long sF = (long long)T_ * T_;

    dim3 blk(256);

    // 1) projections: P = W[I,C] @ x_b[C,T] + bias    (M=I, N=T, K=C)
    dim3 grd_p(T_ / BN, I_ / BM, B_);
    gemm_f32x2<false, 1><<<grd_p, blk>>>(g_w,  x, pg, g_b,  nullptr, nullptr,
        C_, C_, T_, T_, 0, sX, sP, 0, 0);
    gemm_f32x2<false, 1><<<grd_p, blk>>>(th_w, x, pt, th_b, nullptr, nullptr,
        C_, C_, T_, T_, 0, sX, sP, 0, 0);
    gemm_f32x2<false, 1><<<grd_p, blk>>>(ph_w, x, pp, ph_b, nullptr, nullptr,
        C_, C_, T_, T_, 0, sX, sP, 0, 0);

    // 2) scores^T: fT[s,t] = sum_i phi[i,s] * theta[i,t]  (M=T(s), N=T(t), K=I)
    dim3 grd_f(T_ / BN, T_ / BM, B_);
    gemm_f32x2<true, 0><<<grd_f, blk>>>(pp, pt, at, nullptr, nullptr, nullptr,
        I_, T_, T_, T_, sP, sP, sF, 0, 0);

    // 3) column softmax over s; store exp unnormalized + invZ[b,t]
    softmax_cols<<<dim3(T_ / 32, B_), dim3(32, 8)>>>(at, iz);

    // 4) y'[i,t] = sum_s g[i,s] * E[s,t]   (NN: M=I, N=T, K=T)
    dim3 grd_y(T_ / BN, I_ / BM, B_);
    gemm_f32x2<false, 0><<<grd_y, blk>>>(pg, at, yv, nullptr, nullptr, nullptr,
        T_, T_, T_, T_, sP, sF, sP, 0, 0);

    // 5) s = (W_w[C,I] @ y'_b[I,T]) * invZ[t] + W_b + x   (M=C, N=T, K=I)
    dim3 grd_o(T_ / BN, C_ / BM, B_);
    gemm_f32x2<false, 7><<<grd_o, blk>>>(W_w, yv, out, W_b, x, iz,
        I_, I_, T_, T_, 0, sP, sX, sX, (long long)T_);

    // 6) batchnorm stats + apply (in place on d_out)
    bn_stats<<<C_, blk>>>(out, mean, rstd);
    bn_apply<<<B_ * C_, blk>>>(out, mean, rstd, gamma, beta);
}

// round 3
// speedup vs baseline: 1.0006x; 1.0006x over previous
#include <cuda_runtime.h>
#include <math.h>
#include <stdint.h>

#define B_ 8
#define C_ 1024
#define T_ 2048
#define I_ 512
#define BN_EPS 1e-5f

typedef unsigned long long u64;

// ---------------- static scratch (allocation-free) ----------------
__device__ float g_pg[B_ * I_ * T_];                 // g projection   [B,I,T]
__device__ float g_pt[B_ * I_ * T_];                 // theta proj     [B,I,T]
__device__ float g_pp[B_ * I_ * T_];                 // phi proj       [B,I,T]
__device__ float g_at[(long long)B_ * T_ * T_];      // scores^T / exp [B,S,T]
__device__ float g_yv[B_ * I_ * T_];                 // y' (unnormalized) [B,I,T]
__device__ float g_z[B_ * T_];                       // 1/Z per (b,t)
__device__ float g_mean[C_];
__device__ float g_rstd[C_];

// ---------------- packed-f32x2 GEMM ----------------
#define BM 128
#define BN 128
#define BK 8

#define FMA2(d, a, b) asm("fma.rn.f32x2 %0, %1, %2, %0;" : "+l"(d) : "l"(a), "l"(b))
#define LDSV2(x, y, addr) \
    asm volatile("ld.shared.v2.u64 {%0, %1}, [%2];" : "=l"(x), "=l"(y) : "r"(addr))

__device__ __forceinline__ float lo32(u64 v) { return __uint_as_float((unsigned)v); }
__device__ __forceinline__ float hi32(u64 v) { return __uint_as_float((unsigned)(v >> 32)); }

// C[z] = op(A[z]) * B[z]  (+ epilogue)
// TA=false: A[m*lda+k] (weights, row-major, k contiguous)
// TA=true : A[k*lda+m] (activation, m contiguous)
// B always B[k*ldb+n] (n contiguous)
// EPI bitmask: 1=+bias[m], 2=+resid, 4=*colscale[n]
template <bool TA, int EPI>
__global__ __launch_bounds__(256, 2)
void gemm_f32x2(const float* __restrict__ A, const float* __restrict__ Bm,
                float* __restrict__ Cm,
                const float* __restrict__ bias, const float* __restrict__ resid,
                const float* __restrict__ zscale,
                int K, int lda, int ldb, int ldc,
                long long sA, long long sB, long long sC, long long sR, long long sZ)
{
    __shared__ float As[2][BK][BM];         // 8 KB
    __shared__ float Bsd[2][BK][2 * BN];    // 16 KB (column-duplicated)

    const int tid = threadIdx.x;
    const int bm0 = blockIdx.y * BM;
    const int bn0 = blockIdx.x * BN;

    A  += sA * blockIdx.z;
    Bm += sB * blockIdx.z;
    Cm += sC * blockIdx.z;

    const int tr = tid >> 4;   // 0..15 row group
    const int tc = tid & 15;   // 0..15 col group

    u64 acc[4][8];
#pragma unroll
    for (int i = 0; i < 4; i++)
#pragma unroll
        for (int j = 0; j < 8; j++) acc[i][j] = 0ull;

    const uint32_t as_base = (uint32_t)__cvta_generic_to_shared(&As[0][0][0]);
    const uint32_t bs_base = (uint32_t)__cvta_generic_to_shared(&Bsd[0][0][0]);

    // ---- tile loaders (global -> regs -> smem) ----
    float4 ra, rb;
    auto load_tile = [&](int k0) {
        if (TA) {
            int k = tid >> 5, mg = (tid & 31) << 2;
            ra = *(const float4*)&A[(long long)(k0 + k) * lda + bm0 + mg];
        } else {
            int m = tid >> 1, kg = (tid & 1) << 2;
            ra = *(const float4*)&A[(long long)(bm0 + m) * lda + k0 + kg];
        }
        int kb = tid >> 5, ng = (tid & 31) << 2;
        rb = *(const float4*)&Bm[(long long)(k0 + kb) * ldb + bn0 + ng];
    };
    auto store_tile = [&](int buf) {
        if (TA) {
            int k = tid >> 5, mg = (tid & 31) << 2;
            *(float4*)&As[buf][k][mg] = ra;
        } else {
            int m = tid >> 1, kg = (tid & 1) << 2;
            As[buf][kg + 0][m] = ra.x;
            As[buf][kg + 1][m] = ra.y;
            As[buf][kg + 2][m] = ra.z;
            As[buf][kg + 3][m] = ra.w;
        }
        int kb = tid >> 5, ng = (tid & 31) << 2;
        *(float4*)&Bsd[buf][kb][2 * ng]     = make_float4(rb.x, rb.x, rb.y, rb.y);
        *(float4*)&Bsd[buf][kb][2 * ng + 4] = make_float4(rb.z, rb.z, rb.w, rb.w);
    };

    // prologue
    load_tile(0);
    store_tile(0);
    __syncthreads();

    const int ntiles = K / BK;
    int buf = 0;
    for (int t = 0; t < ntiles; t++) {
        const bool has_next = (t + 1 < ntiles);
        if (has_next) load_tile((t + 1) * BK);

        const uint32_t a_tile = as_base + buf * (BK * BM * 4);
        const uint32_t b_tile = bs_base + buf * (BK * 2 * BN * 4);
#pragma unroll
        for (int k = 0; k < BK; k++) {
            u64 a2[4], bb[8];
            uint32_t aa = a_tile + (k * BM + tr * 4) * 4;
            LDSV2(a2[0], a2[1], aa);
            LDSV2(a2[2], a2[3], aa + 256);           // +64 rows
            uint32_t ba = b_tile + k * (2 * BN * 4) + tc * 32;
            LDSV2(bb[0], bb[1], ba);
            LDSV2(bb[2], bb[3], ba + 16);
            LDSV2(bb[4], bb[5], ba + 512);           // +64 cols (dup)
            LDSV2(bb[6], bb[7], ba + 528);
#pragma unroll
            for (int rp = 0; rp < 4; rp++)
#pragma unroll
                for (int j = 0; j < 8; j++)
                    FMA2(acc[rp][j], a2[rp], bb[j]);
        }

        if (has_next) store_tile(buf ^ 1);
        __syncthreads();
        buf ^= 1;
    }

    // ---- epilogue ----
    const float* zrow = (EPI & 4) ? (zscale + sZ * blockIdx.z) : nullptr;
    const float* rbase = (EPI & 2) ? (resid + sR * blockIdx.z) : nullptr;
    const int n0 = bn0 + tc * 4;
    const int n1 = n0 + 64;
#pragma unroll
    for (int rp = 0; rp < 4; rp++) {
        const int mrel = ((rp >> 1) ? 64 : 0) + tr * 4 + (rp & 1) * 2;
#pragma unroll
        for (int h = 0; h < 2; h++) {
            const int m = bm0 + mrel + h;
            const long long rowoff = (long long)m * ldc;
            float v[8];
#pragma unroll
            for (int j = 0; j < 8; j++)
                v[j] = h ? hi32(acc[rp][j]) : lo32(acc[rp][j]);
            if (EPI & 4) {
#pragma unroll
                for (int j = 0; j < 4; j++) { v[j] *= zrow[n0 + j]; v[4 + j] *= zrow[n1 + j]; }
            }
            if (EPI & 1) {
                const float bv = bias[m];
#pragma unroll
                for (int j = 0; j < 8; j++) v[j] += bv;
            }
            if (EPI & 2) {
#pragma unroll
                for (int j = 0; j < 4; j++) {
                    v[j]     += rbase[rowoff + n0 + j];
                    v[4 + j] += rbase[rowoff + n1 + j];
                }
            }
            *(float4*)&Cm[rowoff + n0] = make_float4(v[0], v[1], v[2], v[3]);
            *(float4*)&Cm[rowoff + n1] = make_float4(v[4], v[5], v[6], v[7]);
        }
    }
}

// ---------------- column softmax (over s) on fT[b][s][t]; stores exp, invZ ----
__global__ __launch_bounds__(256)
void softmax_cols(float* __restrict__ f, float* __restrict__ invZ)
{
    const int b = blockIdx.y;
    const int t = blockIdx.x * 32 + threadIdx.x;
    const int ty = threadIdx.y;  // 0..7
    float* fb = f + (long long)b * T_ * T_;

    float mx = -1e30f;
#pragma unroll 8
    for (int s = ty; s < T_; s += 8)
        mx = fmaxf(mx, fb[(long long)s * T_ + t]);

    __shared__ float red1[8][32];
    __shared__ float red2[8][32];
    red1[ty][threadIdx.x] = mx;
    __syncthreads();
#pragma unroll
    for (int i = 0; i < 8; i++) mx = fmaxf(mx, red1[i][threadIdx.x]);

    float sum = 0.0f;
#pragma unroll 8
    for (int s = ty; s < T_; s += 8) {
        const long long idx = (long long)s * T_ + t;
        const float v = __expf(fb[idx] - mx);
        fb[idx] = v;
        sum += v;
    }
    red2[ty][threadIdx.x] = sum;
    __syncthreads();
    if (ty == 0) {
        float tot = 0.0f;
#pragma unroll
        for (int i = 0; i < 8; i++) tot += red2[i][threadIdx.x];
        invZ[(long long)b * T_ + t] = 1.0f / tot;
    }
}

// ---------------- batchnorm ----------------
__global__ __launch_bounds__(256)
void bn_stats(const float* __restrict__ s, float* __restrict__ mean,
              float* __restrict__ rstd)
{
    const int c = blockIdx.x;
    const int tid = threadIdx.x;
    float sum = 0.0f, sq = 0.0f;
    for (int idx = tid; idx < B_ * T_; idx += 256) {
        int b = idx >> 11;
        int t = idx & (T_ - 1);
        float v = s[(long long)b * C_ * T_ + (long long)c * T_ + t];
        sum += v;
        sq = fmaf(v, v, sq);
    }
    __shared__ float r1[256], r2[256];
    r1[tid] = sum; r2[tid] = sq;
    __syncthreads();
#pragma unroll
    for (int st = 128; st > 0; st >>= 1) {
        if (tid < st) { r1[tid] += r1[tid + st]; r2[tid] += r2[tid + st]; }
        __syncthreads();
    }
    if (tid == 0) {
        const float inv_n = 1.0f / (float)(B_ * T_);
        float m = r1[0] * inv_n;
        float var = r2[0] * inv_n - m * m;
        mean[c] = m;
        rstd[c] = rsqrtf(var + BN_EPS);
    }
}

__global__ __launch_bounds__(256)
void bn_apply(float* __restrict__ s, const float* __restrict__ mean,
              const float* __restrict__ rstd, const float* __restrict__ gamma,
              const float* __restrict__ beta)
{
    const int bc = blockIdx.x;
    const int c = bc & (C_ - 1);
    const long long base = (long long)bc * T_;
    const float m = mean[c], r = rstd[c], g = gamma[c], be = beta[c];
    for (int t = threadIdx.x; t < T_; t += 256)
        s[base + t] = fmaf((s[base + t] - m) * r, g, be);
}

// ---------------- launcher ----------------
extern "C" void kernel_launch(void* const* d_in, const int* in_sizes, int n_in,
                              void* d_out, int out_size)
{
    const float* x     = (const float*)d_in[0];
    const float* g_w   = (const float*)d_in[1];
    const float* g_b   = (const float*)d_in[2];
    const float* th_w  = (const float*)d_in[3];
    const float* th_b  = (const float*)d_in[4];
    const float* ph_w  = (const float*)d_in[5];
    const float* ph_b  = (const float*)d_in[6];
    const float* W_w   = (const float*)d_in[7];
    const float* W_b   = (const float*)d_in[8];
    const float* gamma = (const float*)d_in[9];
    const float* beta  = (const float*)d_in[10];
    float* out = (float*)d_out;

    float *pg, *pt, *pp, *at, *yv, *iz, *mean, *rstd;
    cudaGetSymbolAddress((void**)&pg, g_pg);
    cudaGetSymbolAddress((void**)&pt, g_pt);
    cudaGetSymbolAddress((void**)&pp, g_pp);
    cudaGetSymbolAddress((void**)&at, g_at);
    cudaGetSymbolAddress((void**)&yv, g_yv);
    cudaGetSymbolAddress((void**)&iz, g_z);
    cudaGetSymbolAddress((void**)&mean, g_mean);
    cudaGetSymbolAddress((void**)&rstd, g_rstd);

    const long long sX = (long long)C_ * T_;
    const long long sP = (long long)I_ * T_;
    const long long sF = (long long)T_ * T_;

    dim3 blk(256);

    // 1) projections: P = W[I,C] @ x_b[C,T] + bias    (M=I, N=T, K=C)
    dim3 grd_p(T_ / BN, I_ / BM, B_);
    gemm_f32x2<false, 1><<<grd_p, blk>>>(g_w,  x, pg, g_b,  nullptr, nullptr,
        C_, C_, T_, T_, 0, sX, sP, 0, 0);
    gemm_f32x2<false, 1><<<grd_p, blk>>>(th_w, x, pt, th_b, nullptr, nullptr,
        C_, C_, T_, T_, 0, sX, sP, 0, 0);
    gemm_f32x2<false, 1><<<grd_p, blk>>>(ph_w, x, pp, ph_b, nullptr, nullptr,
        C_, C_, T_, T_, 0, sX, sP, 0, 0);

    // 2) scores^T: fT[s,t] = sum_i phi[i,s] * theta[i,t]  (M=T(s), N=T(t), K=I)
    dim3 grd_f(T_ / BN, T_ / BM, B_);
    gemm_f32x2<true, 0><<<grd_f, blk>>>(pp, pt, at, nullptr, nullptr, nullptr,
        I_, T_, T_, T_, sP, sP, sF, 0, 0);

    // 3) column softmax over s; store exp unnormalized + invZ[b,t]
    softmax_cols<<<dim3(T_ / 32, B_), dim3(32, 8)>>>(at, iz);

    // 4) y'[i,t] = sum_s g[i,s] * E[s,t]   (NN: M=I, N=T, K=T)
    dim3 grd_y(T_ / BN, I_ / BM, B_);
    gemm_f32x2<false, 0><<<grd_y, blk>>>(pg, at, yv, nullptr, nullptr, nullptr,
        T_, T_, T_, T_, sP, sF, sP, 0, 0);

    // 5) s = (W_w[C,I] @ y'_b[I,T]) * invZ[t] + W_b + x   (M=C, N=T, K=I)
    dim3 grd_o(T_ / BN, C_ / BM, B_);
    gemm_f32x2<false, 7><<<grd_o, blk>>>(W_w, yv, out, W_b, x, iz,
        I_, I_, T_, T_, 0, sP, sX, sX, (long long)T_);

    // 6) batchnorm stats + apply (in place on d_out)
    bn_stats<<<C_, blk>>>(out, mean, rstd);
    bn_apply<<<B_ * C_, blk>>>(out, mean, rstd, gamma, beta);
}

// round 5
// speedup vs baseline: 3.2700x; 3.2681x over previous
#include <cuda_runtime.h>
#include <cuda_bf16.h>
#include <math.h>
#include <stdint.h>

#define B_ 8
#define C_ 1024
#define T_ 2048
#define I_ 512
#define BN_EPS 1e-5f

typedef __nv_bfloat16 bf16;

// ================= static scratch =================
__device__ __align__(16) bf16 g_xTh[B_ * T_ * C_];
__device__ __align__(16) bf16 g_xTl[B_ * T_ * C_];
__device__ __align__(16) bf16 g_wgh[I_ * C_],  g_wgl[I_ * C_];
__device__ __align__(16) bf16 g_wth[I_ * C_],  g_wtl[I_ * C_];
__device__ __align__(16) bf16 g_wph[I_ * C_],  g_wpl[I_ * C_];
__device__ __align__(16) bf16 g_Wh[C_ * I_],   g_Wl[C_ * I_];
__device__ __align__(16) bf16 g_gh[B_ * I_ * T_], g_gl[B_ * I_ * T_];
__device__ __align__(16) bf16 g_thh[B_ * T_ * I_], g_thl[B_ * T_ * I_];
__device__ __align__(16) bf16 g_phh[B_ * T_ * I_], g_phl[B_ * T_ * I_];
__device__ __align__(16) float g_f[33554432];               // [B,T,S] fp32
__device__ __align__(16) bf16 g_Eh[33554432], g_El[33554432];
__device__ __align__(16) bf16 g_yTh[B_ * T_ * I_], g_yTl[B_ * T_ * I_];
__device__ float g_mean[C_], g_rstd[C_];

// ================= PTX helpers (baseline features only) =================
#define LDSM4(r, a) \
    asm volatile("ldmatrix.sync.aligned.m8n8.x4.shared.b16 {%0,%1,%2,%3}, [%4];" \
        : "=r"((r)[0]), "=r"((r)[1]), "=r"((r)[2]), "=r"((r)[3]) : "r"(a))

#define MMA16816(c, a, b) \
    asm volatile("mma.sync.aligned.m16n8k16.row.col.f32.bf16.bf16.f32 " \
        "{%0,%1,%2,%3}, {%4,%5,%6,%7}, {%8,%9}, {%0,%1,%2,%3};" \
        : "+f"((c)[0]), "+f"((c)[1]), "+f"((c)[2]), "+f"((c)[3]) \
        : "r"((a)[0]), "r"((a)[1]), "r"((a)[2]), "r"((a)[3]), \
          "r"((b)[0]), "r"((b)[1]))

#define CP_ASYNC16(saddr, gptr) \
    asm volatile("cp.async.cg.shared.global [%0], [%1], 16;" \
        :: "r"(saddr), "l"(__cvta_generic_to_global(gptr)))
#define CP_COMMIT() asm volatile("cp.async.commit_group;" ::: "memory")
#define CP_WAIT0()  asm volatile("cp.async.wait_group 0;" ::: "memory")

// ================= bf16-split MMA GEMM: CTA tile 128x128, K-chunk 32 ========
// D[m,n] = sum_k A[m,k]*B[n,k].  A/B split hi/lo bf16, K-major rows.
// EPI: 0 fp32 | 1 split+bias[m] | 2 split+bias[n] | 3 fp32+bias[m]+resid | 4 split
// products: 0:Ah*Bh  1:Ah*Bl  2:Al*Bh  3:Al*Bl (NPROD of them)
#define ROWB 80                      // padded row stride bytes (32 bf16 -> 80B)
#define COMPB (128 * ROWB)           // 10240 bytes per component tile
#define BUFB (4 * COMPB)             // 40960 per buffer
#define SMEM_BYTES (2 * BUFB)        // 81920

template <int EPI, int NPROD>
__global__ __launch_bounds__(256, 1)
void mma_gemm(const bf16* __restrict__ Ah, const bf16* __restrict__ Al,
              const bf16* __restrict__ Bh, const bf16* __restrict__ Bl,
              float* __restrict__ Cf, bf16* __restrict__ Coh, bf16* __restrict__ Col,
              const float* __restrict__ bias, const float* __restrict__ resid,
              int K, int ldc,
              long long sA, long long sB, long long sC, long long sR)
{
    extern __shared__ char sm[];
    const uint32_t sbase = (uint32_t)__cvta_generic_to_shared(sm);
    const int tid = threadIdx.x;
    const int lane = tid & 31;
    const int wid = tid >> 5;
    const int bm0 = blockIdx.y * 128;
    const int bn0 = blockIdx.x * 128;
    const int z = blockIdx.z;

    const bf16* gp[4];
    gp[0] = Ah + sA * z + (long long)bm0 * K;
    gp[1] = Al + sA * z + (long long)bm0 * K;
    gp[2] = Bh + sB * z + (long long)bn0 * K;
    gp[3] = Bl + sB * z + (long long)bn0 * K;

    const int wm = (wid >> 1) * 32;
    const int wn = (wid & 1) * 64;

    float acc[2][8][4];
#pragma unroll
    for (int i = 0; i < 2; i++)
#pragma unroll
        for (int j = 0; j < 8; j++)
#pragma unroll
            for (int q = 0; q < 4; q++) acc[i][j][q] = 0.0f;

    auto load_chunk = [&](int k0, int buf) {
        const uint32_t b = sbase + buf * BUFB;
#pragma unroll
        for (int i = 0; i < 8; i++) {
            const int u = tid + i * 256;
            const int comp = u >> 9;          // 512 16B-units per component
            const int rem = u & 511;
            const int row = rem >> 2;
            const int un = rem & 3;
            const bf16* g = gp[comp] + (long long)row * K + k0 + un * 8;
            const uint32_t s = b + comp * COMPB + row * ROWB + un * 16;
            CP_ASYNC16(s, g);
        }
        CP_COMMIT();
    };

    auto compute = [&](int buf) {
        const uint32_t b = sbase + buf * BUFB;
        const uint32_t arow = wm + (lane & 15);
        const uint32_t akoff = ((lane >> 4) & 1) * 16;
        const uint32_t brow = wn + ((lane >> 4) << 3) + (lane & 7);
        const uint32_t bkoff = ((lane >> 3) & 1) * 16;
#pragma unroll
        for (int s = 0; s < 2; s++) {          // two k16 steps in a k32 chunk
            uint32_t ah[2][4], al[2][4], bh[8][2], bl[8][2];
#pragma unroll
            for (int mt = 0; mt < 2; mt++) {
                const uint32_t addr = b + (arow + mt * 16) * ROWB + s * 32 + akoff;
                LDSM4(ah[mt], addr);
                LDSM4(al[mt], addr + COMPB);
            }
#pragma unroll
            for (int np = 0; np < 4; np++) {   // 4 x n16 groups = n64
                const uint32_t addr = b + 2 * COMPB + (brow + np * 16) * ROWB
                                      + s * 32 + bkoff;
                uint32_t r[4];
                LDSM4(r, addr);
                bh[np*2][0] = r[0]; bh[np*2][1] = r[1];
                bh[np*2+1][0] = r[2]; bh[np*2+1][1] = r[3];
                LDSM4(r, addr + COMPB);
                bl[np*2][0] = r[0]; bl[np*2][1] = r[1];
                bl[np*2+1][0] = r[2]; bl[np*2+1][1] = r[3];
            }
#pragma unroll
            for (int mt = 0; mt < 2; mt++)
#pragma unroll
                for (int nt = 0; nt < 8; nt++) {
                    MMA16816(acc[mt][nt], ah[mt], bh[nt]);
                    if (NPROD > 1) MMA16816(acc[mt][nt], ah[mt], bl[nt]);
                    if (NPROD > 2) MMA16816(acc[mt][nt], al[mt], bh[nt]);
                    if (NPROD > 3) MMA16816(acc[mt][nt], al[mt], bl[nt]);
                }
        }
    };

    const int nch = K / 32;
    load_chunk(0, 0);
    int buf = 0;
    for (int c = 0; c < nch; c++) {
        CP_WAIT0();
        __syncthreads();
        if (c + 1 < nch) load_chunk((c + 1) * 32, buf ^ 1);
        compute(buf);
        buf ^= 1;
    }

    // ================= epilogue =================
    const int r0 = lane >> 2;
    const int cq = (lane & 3) * 2;
#pragma unroll
    for (int mt = 0; mt < 2; mt++) {
        const int mA = bm0 + wm + mt * 16 + r0;
        const int mB = mA + 8;
        float biasA = 0.0f, biasB = 0.0f;
        if (EPI == 1 || EPI == 3) { biasA = bias[mA]; biasB = bias[mB]; }
        const long long rowA = sC * z + (long long)mA * ldc;
        const long long rowB = sC * z + (long long)mB * ldc;
#pragma unroll
        for (int nt = 0; nt < 8; nt++) {
            const int n = bn0 + wn + nt * 8 + cq;
            float v0 = acc[mt][nt][0], v1 = acc[mt][nt][1];
            float v2 = acc[mt][nt][2], v3 = acc[mt][nt][3];
            if (EPI == 2) {
                const float bn0v = bias[n], bn1v = bias[n + 1];
                v0 += bn0v; v1 += bn1v; v2 += bn0v; v3 += bn1v;
            }
            if (EPI == 1 || EPI == 3) { v0 += biasA; v1 += biasA; v2 += biasB; v3 += biasB; }
            if (EPI == 0 || EPI == 3) {
                if (EPI == 3) {
                    const long long rA = sR * z + (long long)mA * ldc + n;
                    const long long rB = sR * z + (long long)mB * ldc + n;
                    float2 ra = *(const float2*)(resid + rA);
                    float2 rb = *(const float2*)(resid + rB);
                    v0 += ra.x; v1 += ra.y; v2 += rb.x; v3 += rb.y;
                }
                *(float2*)(Cf + rowA + n) = make_float2(v0, v1);
                *(float2*)(Cf + rowB + n) = make_float2(v2, v3);
            } else {
                __nv_bfloat162 hA = __floats2bfloat162_rn(v0, v1);
                __nv_bfloat162 hB = __floats2bfloat162_rn(v2, v3);
                __nv_bfloat162 lA = __floats2bfloat162_rn(
                    v0 - __bfloat162float(hA.x), v1 - __bfloat162float(hA.y));
                __nv_bfloat162 lB = __floats2bfloat162_rn(
                    v2 - __bfloat162float(hB.x), v3 - __bfloat162float(hB.y));
                *(__nv_bfloat162*)(Coh + rowA + n) = hA;
                *(__nv_bfloat162*)(Coh + rowB + n) = hB;
                *(__nv_bfloat162*)(Col + rowA + n) = lA;
                *(__nv_bfloat162*)(Col + rowB + n) = lB;
            }
        }
    }
}

// ================= pre-passes =================
__global__ __launch_bounds__(256)
void split_w(const float* __restrict__ s, bf16* __restrict__ h, bf16* __restrict__ l, int n)
{
    int i = blockIdx.x * 256 + threadIdx.x;
    if (i < n) {
        float v = s[i];
        bf16 hi = __float2bfloat16(v);
        h[i] = hi;
        l[i] = __float2bfloat16(v - __bfloat162float(hi));
    }
}

__global__ __launch_bounds__(256)
void transpose_split_x(const float* __restrict__ x, bf16* __restrict__ th, bf16* __restrict__ tl)
{
    __shared__ float tile[32][33];
    const int b = blockIdx.z;
    const int t0 = blockIdx.x * 32, c0 = blockIdx.y * 32;
    const int tx = threadIdx.x, ty = threadIdx.y;  // 32 x 8
    const float* xb = x + (long long)b * C_ * T_;
#pragma unroll
    for (int j = 0; j < 32; j += 8)
        tile[ty + j][tx] = xb[(long long)(c0 + ty + j) * T_ + t0 + tx];
    __syncthreads();
    bf16* thb = th + (long long)b * T_ * C_;
    bf16* tlb = tl + (long long)b * T_ * C_;
#pragma unroll
    for (int j = 0; j < 32; j += 8) {
        float v = tile[tx][ty + j];
        long long o = (long long)(t0 + ty + j) * C_ + c0 + tx;
        bf16 h = __float2bfloat16(v);
        thb[o] = h;
        tlb[o] = __float2bfloat16(v - __bfloat162float(h));
    }
}

// ================= softmax (FFMA-poly exp, rows of f[b*T+t][s]) =============
__device__ __forceinline__ float fast_exp(float x)
{
    float y = x * 1.4426950408889634f;
    float t = y + 12582912.0f;
    int e = __float_as_int(t) - 0x4B400000;
    float r = t - 12582912.0f;
    float f = y - r;
    float pq = 1.5403530393381608e-4f;
    pq = fmaf(pq, f, 1.3333558146428443e-3f);
    pq = fmaf(pq, f, 9.618129107628477e-3f);
    pq = fmaf(pq, f, 5.550410866482158e-2f);
    pq = fmaf(pq, f, 2.402265069591007e-1f);
    pq = fmaf(pq, f, 6.931471805599453e-1f);
    pq = fmaf(pq, f, 1.0f);
    float res = __int_as_float(__float_as_int(pq) + (e << 23));
    return (y > -120.0f) ? res : 0.0f;
}

__global__ __launch_bounds__(256)
void softmax_split(const float* __restrict__ f, bf16* __restrict__ Eh, bf16* __restrict__ El)
{
    const long long base = (long long)blockIdx.x * T_;
    const int tid = threadIdx.x;
    const int lane = tid & 31, w = tid >> 5;
    __shared__ float red[8];

    float v[8];
    float mx = -1e30f;
#pragma unroll
    for (int i = 0; i < 8; i++) {
        v[i] = f[base + tid + i * 256];
        mx = fmaxf(mx, v[i]);
    }
#pragma unroll
    for (int o = 16; o; o >>= 1) mx = fmaxf(mx, __shfl_xor_sync(~0u, mx, o));
    if (lane == 0) red[w] = mx;
    __syncthreads();
    mx = red[0];
#pragma unroll
    for (int i = 1; i < 8; i++) mx = fmaxf(mx, red[i]);
    __syncthreads();

    float sum = 0.0f;
#pragma unroll
    for (int i = 0; i < 8; i++) {
        v[i] = fast_exp(v[i] - mx);
        sum += v[i];
    }
#pragma unroll
    for (int o = 16; o; o >>= 1) sum += __shfl_xor_sync(~0u, sum, o);
    if (lane == 0) red[w] = sum;
    __syncthreads();
    float tot = 0.0f;
#pragma unroll
    for (int i = 0; i < 8; i++) tot += red[i];
    const float inv = 1.0f / tot;

#pragma unroll
    for (int i = 0; i < 8; i++) {
        float e = v[i] * inv;
        bf16 h = __float2bfloat16(e);
        Eh[base + tid + i * 256] = h;
        El[base + tid + i * 256] = __float2bfloat16(e - __bfloat162float(h));
    }
}

// ================= batchnorm =================
__global__ __launch_bounds__(256)
void bn_stats(const float* __restrict__ s, float* __restrict__ mean, float* __restrict__ rstd)
{
    const int c = blockIdx.x;
    const int tid = threadIdx.x;
    float sum = 0.0f, sq = 0.0f;
    for (int idx = tid; idx < B_ * T_; idx += 256) {
        int b = idx >> 11;
        int t = idx & (T_ - 1);
        float v = s[(long long)b * C_ * T_ + (long long)c * T_ + t];
        sum += v;
        sq = fmaf(v, v, sq);
    }
    __shared__ float r1[256], r2[256];
    r1[tid] = sum; r2[tid] = sq;
    __syncthreads();
#pragma unroll
    for (int st = 128; st > 0; st >>= 1) {
        if (tid < st) { r1[tid] += r1[tid + st]; r2[tid] += r2[tid + st]; }
        __syncthreads();
    }
    if (tid == 0) {
        const float inv_n = 1.0f / (float)(B_ * T_);
        float m = r1[0] * inv_n;
        float var = r2[0] * inv_n - m * m;
        mean[c] = m;
        rstd[c] = rsqrtf(var + BN_EPS);
    }
}

__global__ __launch_bounds__(256)
void bn_apply(float* __restrict__ s, const float* __restrict__ mean,
              const float* __restrict__ rstd, const float* __restrict__ gamma,
              const float* __restrict__ beta)
{
    const int bc = blockIdx.x;
    const int c = bc & (C_ - 1);
    const long long base = (long long)bc * T_;
    const float m = mean[c], r = rstd[c], g = gamma[c], be = beta[c];
    for (int t = threadIdx.x; t < T_; t += 256)
        s[base + t] = fmaf((s[base + t] - m) * r, g, be);
}

// ================= launcher =================
extern "C" void kernel_launch(void* const* d_in, const int* in_sizes, int n_in,
                              void* d_out, int out_size)
{
    const float* x     = (const float*)d_in[0];
    const float* g_w   = (const float*)d_in[1];
    const float* g_b   = (const float*)d_in[2];
    const float* th_w  = (const float*)d_in[3];
    const float* th_b  = (const float*)d_in[4];
    const float* ph_w  = (const float*)d_in[5];
    const float* ph_b  = (const float*)d_in[6];
    const float* W_w   = (const float*)d_in[7];
    const float* W_b   = (const float*)d_in[8];
    const float* gamma = (const float*)d_in[9];
    const float* beta  = (const float*)d_in[10];
    float* out = (float*)d_out;

    bf16 *xTh, *xTl, *wgh, *wgl, *wth, *wtl, *wph, *wpl, *Wh, *Wl;
    bf16 *gh, *gl, *thh, *thl, *phh, *phl, *Eh, *El, *yTh, *yTl;
    float *f, *mean, *rstd;
    cudaGetSymbolAddress((void**)&xTh, g_xTh);  cudaGetSymbolAddress((void**)&xTl, g_xTl);
    cudaGetSymbolAddress((void**)&wgh, g_wgh);  cudaGetSymbolAddress((void**)&wgl, g_wgl);
    cudaGetSymbolAddress((void**)&wth, g_wth);  cudaGetSymbolAddress((void**)&wtl, g_wtl);
    cudaGetSymbolAddress((void**)&wph, g_wph);  cudaGetSymbolAddress((void**)&wpl, g_wpl);
    cudaGetSymbolAddress((void**)&Wh, g_Wh);    cudaGetSymbolAddress((void**)&Wl, g_Wl);
    cudaGetSymbolAddress((void**)&gh, g_gh);    cudaGetSymbolAddress((void**)&gl, g_gl);
    cudaGetSymbolAddress((void**)&thh, g_thh);  cudaGetSymbolAddress((void**)&thl, g_thl);
    cudaGetSymbolAddress((void**)&phh, g_phh);  cudaGetSymbolAddress((void**)&phl, g_phl);
    cudaGetSymbolAddress((void**)&Eh, g_Eh);    cudaGetSymbolAddress((void**)&El, g_El);
    cudaGetSymbolAddress((void**)&yTh, g_yTh);  cudaGetSymbolAddress((void**)&yTl, g_yTl);
    cudaGetSymbolAddress((void**)&f, g_f);
    cudaGetSymbolAddress((void**)&mean, g_mean); cudaGetSymbolAddress((void**)&rstd, g_rstd);

    cudaFuncSetAttribute(mma_gemm<0,4>, cudaFuncAttributeMaxDynamicSharedMemorySize, SMEM_BYTES);
    cudaFuncSetAttribute(mma_gemm<1,3>, cudaFuncAttributeMaxDynamicSharedMemorySize, SMEM_BYTES);
    cudaFuncSetAttribute(mma_gemm<2,3>, cudaFuncAttributeMaxDynamicSharedMemorySize, SMEM_BYTES);
    cudaFuncSetAttribute(mma_gemm<3,3>, cudaFuncAttributeMaxDynamicSharedMemorySize, SMEM_BYTES);
    cudaFuncSetAttribute(mma_gemm<4,3>, cudaFuncAttributeMaxDynamicSharedMemorySize, SMEM_BYTES);

    const long long sXT = (long long)T_ * C_;
    const long long sX  = (long long)C_ * T_;
    const long long sTI = (long long)T_ * I_;
    const long long sIT = (long long)I_ * T_;
    const long long sF  = (long long)T_ * T_;

    dim3 blk(256);

    // 0) splits + transpose
    split_w<<<(I_ * C_ + 255) / 256, blk>>>(g_w,  wgh, wgl, I_ * C_);
    split_w<<<(I_ * C_ + 255) / 256, blk>>>(th_w, wth, wtl, I_ * C_);
    split_w<<<(I_ * C_ + 255) / 256, blk>>>(ph_w, wph, wpl, I_ * C_);
    split_w<<<(C_ * I_ + 255) / 256, blk>>>(W_w,  Wh,  Wl,  C_ * I_);
    transpose_split_x<<<dim3(T_ / 32, C_ / 32, B_), dim3(32, 8)>>>(x, xTh, xTl);

    // 1) g[i,t] = sum_c wg[i,c] * xT[t,c] + gb[i]      (M=I,N=T,K=C) EPI1 split
    mma_gemm<1,3><<<dim3(T_ / 128, I_ / 128, B_), blk, SMEM_BYTES>>>(
        wgh, wgl, xTh, xTl, nullptr, gh, gl, g_b, nullptr, C_, T_, 0, sXT, sIT, 0);
    // 2) thT[t,i] = sum_c xT[t,c] * wth[i,c] + thb[i]  (M=T,N=I,K=C) EPI2 split
    mma_gemm<2,3><<<dim3(I_ / 128, T_ / 128, B_), blk, SMEM_BYTES>>>(
        xTh, xTl, wth, wtl, nullptr, thh, thl, th_b, nullptr, C_, I_, sXT, 0, sTI, 0);
    // 3) phT[t,i]
    mma_gemm<2,3><<<dim3(I_ / 128, T_ / 128, B_), blk, SMEM_BYTES>>>(
        xTh, xTl, wph, wpl, nullptr, phh, phl, ph_b, nullptr, C_, I_, sXT, 0, sTI, 0);
    // 4) f[t,s] = sum_i thT[t,i] * phT[s,i]            (M=T,N=T,K=I) EPI0, 4 prod
    mma_gemm<0,4><<<dim3(T_ / 128, T_ / 128, B_), blk, SMEM_BYTES>>>(
        thh, thl, phh, phl, f, nullptr, nullptr, nullptr, nullptr, I_, T_, sTI, sTI, sF, 0);
    // 5) softmax rows -> normalized split E
    softmax_split<<<B_ * T_, blk>>>(f, Eh, El);
    // 6) yT[t,i] = sum_s E[t,s] * g[i,s]               (M=T,N=I,K=T) EPI4 split
    mma_gemm<4,3><<<dim3(I_ / 128, T_ / 128, B_), blk, SMEM_BYTES>>>(
        Eh, El, gh, gl, nullptr, yTh, yTl, nullptr, nullptr, T_, I_, sF, sIT, sTI, 0);
    // 7) s[c,t] = sum_i W[c,i] * yT[t,i] + Wb[c] + x   (M=C,N=T,K=I) EPI3 fp32
    mma_gemm<3,3><<<dim3(T_ / 128, C_ / 128, B_), blk, SMEM_BYTES>>>(
        Wh, Wl, yTh, yTl, out, nullptr, nullptr, W_b, x, I_, T_, 0, sTI, sX, sX);

    // 8) batchnorm
    bn_stats<<<C_, blk>>>(out, mean, rstd);
    bn_apply<<<B_ * C_, blk>>>(out, mean, rstd, gamma, beta);
}

// round 6
// speedup vs baseline: 3.6362x; 1.1120x over previous
#include <cuda_runtime.h>
#include <cuda_bf16.h>
#include <cuda_fp16.h>
#include <math.h>
#include <stdint.h>

#define B_ 8
#define C_ 1024
#define T_ 2048
#define I_ 512
#define BN_EPS 1e-5f

typedef __nv_bfloat16 bf16;

// ================= static scratch =================
__device__ __align__(16) bf16 g_xTh[B_ * T_ * C_];
__device__ __align__(16) bf16 g_xTl[B_ * T_ * C_];
__device__ __align__(16) bf16 g_wgh[I_ * C_],  g_wgl[I_ * C_];
__device__ __align__(16) bf16 g_wth[I_ * C_],  g_wtl[I_ * C_];
__device__ __align__(16) bf16 g_wph[I_ * C_],  g_wpl[I_ * C_];
__device__ __align__(16) bf16 g_Wh[C_ * I_],   g_Wl[C_ * I_];
__device__ __align__(16) __half g_gh[B_ * I_ * T_], g_gl[B_ * I_ * T_];  // fp16 split
__device__ __align__(16) bf16 g_thh[B_ * T_ * I_], g_thl[B_ * T_ * I_];
__device__ __align__(16) bf16 g_phh[B_ * T_ * I_], g_phl[B_ * T_ * I_];
__device__ __align__(16) float g_f[33554432];               // [B,T,S] fp32
__device__ __align__(16) __half g_E[33554432];              // fp16 attention
__device__ __align__(16) bf16 g_yTh[B_ * T_ * I_], g_yTl[B_ * T_ * I_];
__device__ float g_mean[C_], g_rstd[C_];

// ================= PTX helpers (baseline features only) =================
#define LDSM4(r, a) \
    asm volatile("ldmatrix.sync.aligned.m8n8.x4.shared.b16 {%0,%1,%2,%3}, [%4];" \
        : "=r"((r)[0]), "=r"((r)[1]), "=r"((r)[2]), "=r"((r)[3]) : "r"(a))

#define MMA_BF16(c, a, b) \
    asm volatile("mma.sync.aligned.m16n8k16.row.col.f32.bf16.bf16.f32 " \
        "{%0,%1,%2,%3}, {%4,%5,%6,%7}, {%8,%9}, {%0,%1,%2,%3};" \
        : "+f"((c)[0]), "+f"((c)[1]), "+f"((c)[2]), "+f"((c)[3]) \
        : "r"((a)[0]), "r"((a)[1]), "r"((a)[2]), "r"((a)[3]), \
          "r"((b)[0]), "r"((b)[1]))

#define MMA_F16(c, a, b) \
    asm volatile("mma.sync.aligned.m16n8k16.row.col.f32.f16.f16.f32 " \
        "{%0,%1,%2,%3}, {%4,%5,%6,%7}, {%8,%9}, {%0,%1,%2,%3};" \
        : "+f"((c)[0]), "+f"((c)[1]), "+f"((c)[2]), "+f"((c)[3]) \
        : "r"((a)[0]), "r"((a)[1]), "r"((a)[2]), "r"((a)[3]), \
          "r"((b)[0]), "r"((b)[1]))

#define CP_ASYNC16(saddr, gptr) \
    asm volatile("cp.async.cg.shared.global [%0], [%1], 16;" \
        :: "r"(saddr), "l"(__cvta_generic_to_global(gptr)))
#define CP_COMMIT() asm volatile("cp.async.commit_group;" ::: "memory")
#define CP_WAIT0()  asm volatile("cp.async.wait_group 0;" ::: "memory")

// ================= split MMA GEMM: CTA tile 128x128, K-chunk 32 =============
// D[m,n] = sum_k A[m,k]*B[n,k].  K-major rows, 16-bit elements.
// NCOMP=4: smem comps [Ah, Al, Bh, Bl];  NCOMP=3: [Ah, Bh, Bl] (no A-lo).
// Products used (in order): Ah*Bh | Ah*Bl | Al*Bh | Al*Bl  (first NPROD)
// F16: operands are fp16 (else bf16). Accumulation fp32 either way.
// EPI: 0 fp32 | 2 bf16split+bias[n] | 3 fp32+bias[m]+resid | 4 bf16split
//      5 f16split+bias[m]
#define ROWB 80                      // padded row stride bytes (32 elem -> 80B)
#define COMPB (128 * ROWB)           // 10240 bytes per component tile
#define SMEM_MAX (2 * 4 * COMPB)     // 81920

template <int EPI, int NPROD, int NCOMP, bool F16>
__global__ __launch_bounds__(256, 1)
void mma_gemm(const bf16* __restrict__ Ah, const bf16* __restrict__ Al,
              const bf16* __restrict__ Bh, const bf16* __restrict__ Bl,
              float* __restrict__ Cf, void* __restrict__ Coh, void* __restrict__ Col,
              const float* __restrict__ bias, const float* __restrict__ resid,
              int K, int ldc,
              long long sA, long long sB, long long sC, long long sR)
{
    constexpr int BUFB = NCOMP * COMPB;
    extern __shared__ char sm[];
    const uint32_t sbase = (uint32_t)__cvta_generic_to_shared(sm);
    const int tid = threadIdx.x;
    const int lane = tid & 31;
    const int wid = tid >> 5;
    const int bm0 = blockIdx.y * 128;
    const int bn0 = blockIdx.x * 128;
    const int z = blockIdx.z;

    const bf16* gp[NCOMP];
    gp[0] = Ah + sA * z + (long long)bm0 * K;
    if (NCOMP == 4) {
        gp[1] = Al + sA * z + (long long)bm0 * K;
        gp[2] = Bh + sB * z + (long long)bn0 * K;
        gp[3] = Bl + sB * z + (long long)bn0 * K;
    } else {
        gp[1] = Bh + sB * z + (long long)bn0 * K;
        gp[2] = Bl + sB * z + (long long)bn0 * K;
    }
    constexpr int BC = (NCOMP == 4) ? 2 : 1;   // B hi component index

    const int wm = (wid >> 1) * 32;
    const int wn = (wid & 1) * 64;

    float acc[2][8][4];
#pragma unroll
    for (int i = 0; i < 2; i++)
#pragma unroll
        for (int j = 0; j < 8; j++)
#pragma unroll
            for (int q = 0; q < 4; q++) acc[i][j][q] = 0.0f;

    auto load_chunk = [&](int k0, int buf) {
        const uint32_t b = sbase + buf * BUFB;
#pragma unroll
        for (int i = 0; i < NCOMP * 2; i++) {
            const int u = tid + i * 256;
            const int comp = u >> 9;          // 512 16B-units per component
            const int rem = u & 511;
            const int row = rem >> 2;
            const int un = rem & 3;
            const bf16* g = gp[comp] + (long long)row * K + k0 + un * 8;
            const uint32_t s = b + comp * COMPB + row * ROWB + un * 16;
            CP_ASYNC16(s, g);
        }
        CP_COMMIT();
    };

    auto compute = [&](int buf) {
        const uint32_t b = sbase + buf * BUFB;
        const uint32_t arow = wm + (lane & 15);
        const uint32_t akoff = ((lane >> 4) & 1) * 16;
        const uint32_t brow = wn + ((lane >> 4) << 3) + (lane & 7);
        const uint32_t bkoff = ((lane >> 3) & 1) * 16;
#pragma unroll
        for (int s = 0; s < 2; s++) {          // two k16 steps in a k32 chunk
            uint32_t ah[2][4], al[2][4], bh[8][2], bl[8][2];
#pragma unroll
            for (int mt = 0; mt < 2; mt++) {
                const uint32_t addr = b + (arow + mt * 16) * ROWB + s * 32 + akoff;
                LDSM4(ah[mt], addr);
                if (NPROD > 2) LDSM4(al[mt], addr + COMPB);
            }
#pragma unroll
            for (int np = 0; np < 4; np++) {   // 4 x n16 groups = n64
                const uint32_t addr = b + BC * COMPB + (brow + np * 16) * ROWB
                                      + s * 32 + bkoff;
                uint32_t r[4];
                LDSM4(r, addr);
                bh[np*2][0] = r[0]; bh[np*2][1] = r[1];
                bh[np*2+1][0] = r[2]; bh[np*2+1][1] = r[3];
                if (NPROD > 1) {
                    LDSM4(r, addr + COMPB);
                    bl[np*2][0] = r[0]; bl[np*2][1] = r[1];
                    bl[np*2+1][0] = r[2]; bl[np*2+1][1] = r[3];
                }
            }
#pragma unroll
            for (int mt = 0; mt < 2; mt++)
#pragma unroll
                for (int nt = 0; nt < 8; nt++) {
                    if (F16) {
                        MMA_F16(acc[mt][nt], ah[mt], bh[nt]);
                        if (NPROD > 1) MMA_F16(acc[mt][nt], ah[mt], bl[nt]);
                        if (NPROD > 2) MMA_F16(acc[mt][nt], al[mt], bh[nt]);
                        if (NPROD > 3) MMA_F16(acc[mt][nt], al[mt], bl[nt]);
                    } else {
                        MMA_BF16(acc[mt][nt], ah[mt], bh[nt]);
                        if (NPROD > 1) MMA_BF16(acc[mt][nt], ah[mt], bl[nt]);
                        if (NPROD > 2) MMA_BF16(acc[mt][nt], al[mt], bh[nt]);
                        if (NPROD > 3) MMA_BF16(acc[mt][nt], al[mt], bl[nt]);
                    }
                }
        }
    };

    const int nch = K / 32;
    load_chunk(0, 0);
    int buf = 0;
    for (int c = 0; c < nch; c++) {
        CP_WAIT0();
        __syncthreads();
        if (c + 1 < nch) load_chunk((c + 1) * 32, buf ^ 1);
        compute(buf);
        buf ^= 1;
    }

    // ================= epilogue =================
    const int r0 = lane >> 2;
    const int cq = (lane & 3) * 2;
#pragma unroll
    for (int mt = 0; mt < 2; mt++) {
        const int mA = bm0 + wm + mt * 16 + r0;
        const int mB = mA + 8;
        float biasA = 0.0f, biasB = 0.0f;
        if (EPI == 3 || EPI == 5) { biasA = bias[mA]; biasB = bias[mB]; }
        const long long rowA = sC * z + (long long)mA * ldc;
        const long long rowB = sC * z + (long long)mB * ldc;
#pragma unroll
        for (int nt = 0; nt < 8; nt++) {
            const int n = bn0 + wn + nt * 8 + cq;
            float v0 = acc[mt][nt][0], v1 = acc[mt][nt][1];
            float v2 = acc[mt][nt][2], v3 = acc[mt][nt][3];
            if (EPI == 2) {
                const float bn0v = bias[n], bn1v = bias[n + 1];
                v0 += bn0v; v1 += bn1v; v2 += bn0v; v3 += bn1v;
            }
            if (EPI == 3 || EPI == 5) { v0 += biasA; v1 += biasA; v2 += biasB; v3 += biasB; }
            if (EPI == 0 || EPI == 3) {
                if (EPI == 3) {
                    const long long rA = sR * z + (long long)mA * ldc + n;
                    const long long rB = sR * z + (long long)mB * ldc + n;
                    float2 ra = *(const float2*)(resid + rA);
                    float2 rb = *(const float2*)(resid + rB);
                    v0 += ra.x; v1 += ra.y; v2 += rb.x; v3 += rb.y;
                }
                *(float2*)(Cf + rowA + n) = make_float2(v0, v1);
                *(float2*)(Cf + rowB + n) = make_float2(v2, v3);
            } else if (EPI == 5) {
                __half2 hA = __floats2half2_rn(v0, v1);
                __half2 hB = __floats2half2_rn(v2, v3);
                __half2 lA = __floats2half2_rn(
                    v0 - __half2float(__low2half(hA)), v1 - __half2float(__high2half(hA)));
                __half2 lB = __floats2half2_rn(
                    v2 - __half2float(__low2half(hB)), v3 - __half2float(__high2half(hB)));
                *(__half2*)((__half*)Coh + rowA + n) = hA;
                *(__half2*)((__half*)Coh + rowB + n) = hB;
                *(__half2*)((__half*)Col + rowA + n) = lA;
                *(__half2*)((__half*)Col + rowB + n) = lB;
            } else {
                __nv_bfloat162 hA = __floats2bfloat162_rn(v0, v1);
                __nv_bfloat162 hB = __floats2bfloat162_rn(v2, v3);
                __nv_bfloat162 lA = __floats2bfloat162_rn(
                    v0 - __bfloat162float(hA.x), v1 - __bfloat162float(hA.y));
                __nv_bfloat162 lB = __floats2bfloat162_rn(
                    v2 - __bfloat162float(hB.x), v3 - __bfloat162float(hB.y));
                *(__nv_bfloat162*)((bf16*)Coh + rowA + n) = hA;
                *(__nv_bfloat162*)((bf16*)Coh + rowB + n) = hB;
                *(__nv_bfloat162*)((bf16*)Col + rowA + n) = lA;
                *(__nv_bfloat162*)((bf16*)Col + rowB + n) = lB;
            }
        }
    }
}

// ================= pre-passes =================
__global__ __launch_bounds__(256)
void split_w(const float* __restrict__ s, bf16* __restrict__ h, bf16* __restrict__ l, int n)
{
    int i = blockIdx.x * 256 + threadIdx.x;
    if (i < n) {
        float v = s[i];
        bf16 hi = __float2bfloat16(v);
        h[i] = hi;
        l[i] = __float2bfloat16(v - __bfloat162float(hi));
    }
}

__global__ __launch_bounds__(256)
void transpose_split_x(const float* __restrict__ x, bf16* __restrict__ th, bf16* __restrict__ tl)
{
    __shared__ float tile[32][33];
    const int b = blockIdx.z;
    const int t0 = blockIdx.x * 32, c0 = blockIdx.y * 32;
    const int tx = threadIdx.x, ty = threadIdx.y;  // 32 x 8
    const float* xb = x + (long long)b * C_ * T_;
#pragma unroll
    for (int j = 0; j < 32; j += 8)
        tile[ty + j][tx] = xb[(long long)(c0 + ty + j) * T_ + t0 + tx];
    __syncthreads();
    bf16* thb = th + (long long)b * T_ * C_;
    bf16* tlb = tl + (long long)b * T_ * C_;
#pragma unroll
    for (int j = 0; j < 32; j += 8) {
        float v = tile[tx][ty + j];
        long long o = (long long)(t0 + ty + j) * C_ + c0 + tx;
        bf16 h = __float2bfloat16(v);
        thb[o] = h;
        tlb[o] = __float2bfloat16(v - __bfloat162float(h));
    }
}

// ================= softmax (FFMA-poly exp, rows of f[b*T+t][s]) =============
__device__ __forceinline__ float fast_exp(float x)
{
    float y = x * 1.4426950408889634f;
    float t = y + 12582912.0f;
    int e = __float_as_int(t) - 0x4B400000;
    float r = t - 12582912.0f;
    float f = y - r;
    float pq = 1.5403530393381608e-4f;
    pq = fmaf(pq, f, 1.3333558146428443e-3f);
    pq = fmaf(pq, f, 9.618129107628477e-3f);
    pq = fmaf(pq, f, 5.550410866482158e-2f);
    pq = fmaf(pq, f, 2.402265069591007e-1f);
    pq = fmaf(pq, f, 6.931471805599453e-1f);
    pq = fmaf(pq, f, 1.0f);
    float res = __int_as_float(__float_as_int(pq) + (e << 23));
    return (y > -120.0f) ? res : 0.0f;
}

__global__ __launch_bounds__(256)
void softmax_f16(const float* __restrict__ f, __half* __restrict__ E)
{
    const long long base = (long long)blockIdx.x * T_;
    const int tid = threadIdx.x;
    const int lane = tid & 31, w = tid >> 5;
    __shared__ float red[8];

    float v[8];
    float mx = -1e30f;
#pragma unroll
    for (int i = 0; i < 8; i++) {
        v[i] = f[base + tid + i * 256];
        mx = fmaxf(mx, v[i]);
    }
#pragma unroll
    for (int o = 16; o; o >>= 1) mx = fmaxf(mx, __shfl_xor_sync(~0u, mx, o));
    if (lane == 0) red[w] = mx;
    __syncthreads();
    mx = red[0];
#pragma unroll
    for (int i = 1; i < 8; i++) mx = fmaxf(mx, red[i]);
    __syncthreads();

    float sum = 0.0f;
#pragma unroll
    for (int i = 0; i < 8; i++) {
        v[i] = fast_exp(v[i] - mx);
        sum += v[i];
    }
#pragma unroll
    for (int o = 16; o; o >>= 1) sum += __shfl_xor_sync(~0u, sum, o);
    if (lane == 0) red[w] = sum;
    __syncthreads();
    float tot = 0.0f;
#pragma unroll
    for (int i = 0; i < 8; i++) tot += red[i];
    const float inv = 1.0f / tot;

#pragma unroll
    for (int i = 0; i < 8; i++)
        E[base + tid + i * 256] = __float2half_rn(v[i] * inv);
}

// ================= batchnorm =================
__global__ __launch_bounds__(256)
void bn_stats(const float* __restrict__ s, float* __restrict__ mean, float* __restrict__ rstd)
{
    const int c = blockIdx.x;
    const int tid = threadIdx.x;
    float sum = 0.0f, sq = 0.0f;
    for (int idx = tid; idx < B_ * T_; idx += 256) {
        int b = idx >> 11;
        int t = idx & (T_ - 1);
        float v = s[(long long)b * C_ * T_ + (long long)c * T_ + t];
        sum += v;
        sq = fmaf(v, v, sq);
    }
    __shared__ float r1[256], r2[256];
    r1[tid] = sum; r2[tid] = sq;
    __syncthreads();
#pragma unroll
    for (int st = 128; st > 0; st >>= 1) {
        if (tid < st) { r1[tid] += r1[tid + st]; r2[tid] += r2[tid + st]; }
        __syncthreads();
    }
    if (tid == 0) {
        const float inv_n = 1.0f / (float)(B_ * T_);
        float m = r1[0] * inv_n;
        float var = r2[0] * inv_n - m * m;
        mean[c] = m;
        rstd[c] = rsqrtf(var + BN_EPS);
    }
}

__global__ __launch_bounds__(256)
void bn_apply(float* __restrict__ s, const float* __restrict__ mean,
              const float* __restrict__ rstd, const float* __restrict__ gamma,
              const float* __restrict__ beta)
{
    const int bc = blockIdx.x;
    const int c = bc & (C_ - 1);
    const long long base = (long long)bc * T_;
    const float m = mean[c], r = rstd[c], g = gamma[c], be = beta[c];
    for (int t = threadIdx.x; t < T_; t += 256)
        s[base + t] = fmaf((s[base + t] - m) * r, g, be);
}

// ================= launcher =================
extern "C" void kernel_launch(void* const* d_in, const int* in_sizes, int n_in,
                              void* d_out, int out_size)
{
    const float* x     = (const float*)d_in[0];
    const float* g_w   = (const float*)d_in[1];
    const float* g_b   = (const float*)d_in[2];
    const float* th_w  = (const float*)d_in[3];
    const float* th_b  = (const float*)d_in[4];
    const float* ph_w  = (const float*)d_in[5];
    const float* ph_b  = (const float*)d_in[6];
    const float* W_w   = (const float*)d_in[7];
    const float* W_b   = (const float*)d_in[8];
    const float* gamma = (const float*)d_in[9];
    const float* beta  = (const float*)d_in[10];
    float* out = (float*)d_out;

    bf16 *xTh, *xTl, *wgh, *wgl, *wth, *wtl, *wph, *wpl, *Wh, *Wl;
    bf16 *thh, *thl, *phh, *phl, *yTh, *yTl;
    __half *gh, *gl, *E;
    float *f, *mean, *rstd;
    cudaGetSymbolAddress((void**)&xTh, g_xTh);  cudaGetSymbolAddress((void**)&xTl, g_xTl);
    cudaGetSymbolAddress((void**)&wgh, g_wgh);  cudaGetSymbolAddress((void**)&wgl, g_wgl);
    cudaGetSymbolAddress((void**)&wth, g_wth);  cudaGetSymbolAddress((void**)&wtl, g_wtl);
    cudaGetSymbolAddress((void**)&wph, g_wph);  cudaGetSymbolAddress((void**)&wpl, g_wpl);
    cudaGetSymbolAddress((void**)&Wh, g_Wh);    cudaGetSymbolAddress((void**)&Wl, g_Wl);
    cudaGetSymbolAddress((void**)&gh, g_gh);    cudaGetSymbolAddress((void**)&gl, g_gl);
    cudaGetSymbolAddress((void**)&thh, g_thh);  cudaGetSymbolAddress((void**)&thl, g_thl);
    cudaGetSymbolAddress((void**)&phh, g_phh);  cudaGetSymbolAddress((void**)&phl, g_phl);
    cudaGetSymbolAddress((void**)&E, g_E);
    cudaGetSymbolAddress((void**)&yTh, g_yTh);  cudaGetSymbolAddress((void**)&yTl, g_yTl);
    cudaGetSymbolAddress((void**)&f, g_f);
    cudaGetSymbolAddress((void**)&mean, g_mean); cudaGetSymbolAddress((void**)&rstd, g_rstd);

    cudaFuncSetAttribute(mma_gemm<0,3,4,false>, cudaFuncAttributeMaxDynamicSharedMemorySize, SMEM_MAX);
    cudaFuncSetAttribute(mma_gemm<2,3,4,false>, cudaFuncAttributeMaxDynamicSharedMemorySize, SMEM_MAX);
    cudaFuncSetAttribute(mma_gemm<3,3,4,false>, cudaFuncAttributeMaxDynamicSharedMemorySize, SMEM_MAX);
    cudaFuncSetAttribute(mma_gemm<4,2,3,true>,  cudaFuncAttributeMaxDynamicSharedMemorySize, SMEM_MAX);
    cudaFuncSetAttribute(mma_gemm<5,3,4,false>, cudaFuncAttributeMaxDynamicSharedMemorySize, SMEM_MAX);

    const long long sXT = (long long)T_ * C_;
    const long long sX  = (long long)C_ * T_;
    const long long sTI = (long long)T_ * I_;
    const long long sIT = (long long)I_ * T_;
    const long long sF  = (long long)T_ * T_;

    const int SM4 = 2 * 4 * COMPB;   // 81920
    const int SM3 = 2 * 3 * COMPB;   // 61440

    dim3 blk(256);

    // 0) splits + transpose
    split_w<<<(I_ * C_ + 255) / 256, blk>>>(g_w,  wgh, wgl, I_ * C_);
    split_w<<<(I_ * C_ + 255) / 256, blk>>>(th_w, wth, wtl, I_ * C_);
    split_w<<<(I_ * C_ + 255) / 256, blk>>>(ph_w, wph, wpl, I_ * C_);
    split_w<<<(C_ * I_ + 255) / 256, blk>>>(W_w,  Wh,  Wl,  C_ * I_);
    transpose_split_x<<<dim3(T_ / 32, C_ / 32, B_), dim3(32, 8)>>>(x, xTh, xTl);

    // 1) g[i,t] = sum_c wg[i,c]*xT[t,c] + gb[i]   (M=I,N=T,K=C) -> fp16 split
    mma_gemm<5,3,4,false><<<dim3(T_ / 128, I_ / 128, B_), blk, SM4>>>(
        wgh, wgl, xTh, xTl, nullptr, gh, gl, g_b, nullptr, C_, T_, 0, sXT, sIT, 0);
    // 2) thT[t,i] = sum_c xT[t,c]*wth[i,c] + thb[i]  (M=T,N=I,K=C) -> bf16 split
    mma_gemm<2,3,4,false><<<dim3(I_ / 128, T_ / 128, B_), blk, SM4>>>(
        xTh, xTl, wth, wtl, nullptr, thh, thl, th_b, nullptr, C_, I_, sXT, 0, sTI, 0);
    // 3) phT[t,i]
    mma_gemm<2,3,4,false><<<dim3(I_ / 128, T_ / 128, B_), blk, SM4>>>(
        xTh, xTl, wph, wpl, nullptr, phh, phl, ph_b, nullptr, C_, I_, sXT, 0, sTI, 0);
    // 4) f[t,s] = sum_i thT[t,i]*phT[s,i]   (M=T,N=T,K=I) fp32 out, 3 products
    mma_gemm<0,3,4,false><<<dim3(T_ / 128, T_ / 128, B_), blk, SM4>>>(
        thh, thl, phh, phl, f, nullptr, nullptr, nullptr, nullptr, I_, T_, sTI, sTI, sF, 0);
    // 5) softmax rows -> normalized fp16 E
    softmax_f16<<<B_ * T_, blk>>>(f, E);
    // 6) yT[t,i] = sum_s E[t,s]*g[i,s]   (M=T,N=I,K=T) f16 in, 2 products, bf16 split out
    mma_gemm<4,2,3,true><<<dim3(I_ / 128, T_ / 128, B_), blk, SM3>>>(
        (const bf16*)E, nullptr, (const bf16*)gh, (const bf16*)gl,
        nullptr, yTh, yTl, nullptr, nullptr, T_, I_, sF, sIT, sTI, 0);
    // 7) s[c,t] = sum_i W[c,i]*yT[t,i] + Wb[c] + x   (M=C,N=T,K=I) fp32 + resid
    mma_gemm<3,3,4,false><<<dim3(T_ / 128, C_ / 128, B_), blk, SM4>>>(
        Wh, Wl, yTh, yTl, out, nullptr, nullptr, W_b, x, I_, T_, 0, sTI, sX, sX);

    // 8) batchnorm
    bn_stats<<<C_, blk>>>(out, mean, rstd);
    bn_apply<<<B_ * C_, blk>>>(out, mean, rstd, gamma, beta);
}

// round 7
// speedup vs baseline: 4.1331x; 1.1367x over previous
#include <cuda_runtime.h>
#include <cuda_bf16.h>
#include <cuda_fp16.h>
#include <math.h>
#include <stdint.h>

#define B_ 8
#define C_ 1024
#define T_ 2048
#define I_ 512
#define BN_EPS 1e-5f

typedef __nv_bfloat16 bf16;

// ================= static scratch =================
__device__ __align__(16) bf16   g_xTh[B_ * T_ * C_];
__device__ __align__(16) bf16   g_xTl[B_ * T_ * C_];
__device__ __align__(16) __half g_xT16[B_ * T_ * C_];
__device__ __align__(16) __half g_wg16h[I_ * C_], g_wg16l[I_ * C_];
__device__ __align__(16) bf16   g_wth[I_ * C_],  g_wtl[I_ * C_];
__device__ __align__(16) bf16   g_wph[I_ * C_],  g_wpl[I_ * C_];
__device__ __align__(16) __half g_W16h[C_ * I_], g_W16l[C_ * I_];
__device__ __align__(16) __half g_g16[B_ * I_ * T_];
__device__ __align__(16) bf16   g_thh[B_ * T_ * I_], g_thl[B_ * T_ * I_];
__device__ __align__(16) bf16   g_phh[B_ * T_ * I_], g_phl[B_ * T_ * I_];
__device__ __align__(16) float  g_f[33554432];            // [B,T,S] fp32
__device__ __align__(16) __half g_E[33554432];            // fp16 attention
__device__ __align__(16) __half g_yT16[B_ * T_ * I_];
__device__ float g_mean[C_], g_rstd[C_];

// ================= PTX helpers (baseline features only) =================
#define LDSM4(r, a) \
    asm volatile("ldmatrix.sync.aligned.m8n8.x4.shared.b16 {%0,%1,%2,%3}, [%4];" \
        : "=r"((r)[0]), "=r"((r)[1]), "=r"((r)[2]), "=r"((r)[3]) : "r"(a))

#define MMA_BF16(c, a, b) \
    asm volatile("mma.sync.aligned.m16n8k16.row.col.f32.bf16.bf16.f32 " \
        "{%0,%1,%2,%3}, {%4,%5,%6,%7}, {%8,%9}, {%0,%1,%2,%3};" \
        : "+f"((c)[0]), "+f"((c)[1]), "+f"((c)[2]), "+f"((c)[3]) \
        : "r"((a)[0]), "r"((a)[1]), "r"((a)[2]), "r"((a)[3]), \
          "r"((b)[0]), "r"((b)[1]))

#define MMA_F16(c, a, b) \
    asm volatile("mma.sync.aligned.m16n8k16.row.col.f32.f16.f16.f32 " \
        "{%0,%1,%2,%3}, {%4,%5,%6,%7}, {%8,%9}, {%0,%1,%2,%3};" \
        : "+f"((c)[0]), "+f"((c)[1]), "+f"((c)[2]), "+f"((c)[3]) \
        : "r"((a)[0]), "r"((a)[1]), "r"((a)[2]), "r"((a)[3]), \
          "r"((b)[0]), "r"((b)[1]))

#define CP_ASYNC16(saddr, gptr) \
    asm volatile("cp.async.cg.shared.global [%0], [%1], 16;" \
        :: "r"(saddr), "l"(__cvta_generic_to_global(gptr)))
#define CP_COMMIT() asm volatile("cp.async.commit_group;" ::: "memory")
#define CP_WAIT0()  asm volatile("cp.async.wait_group 0;" ::: "memory")

// ================= split MMA GEMM: CTA tile 128x128, K-chunk 32 =============
// D[m,n] = sum_k A[m,k]*B[n,k].  K-major rows, 16-bit elements.
// MODE 0 (FULL3): comps [Ah,Al,Bh,Bl], products Ah*Bh + Ah*Bl + Al*Bh
// MODE 1 (AB2)  : comps [Ah,Al,B],     products Ah*B  + Al*B
// MODE 2 (SGL)  : comps [A,B],         product  A*B
// EPI: 0 fp32 | 2 bf16 split+bias[n] | 3 fp32+bias[m]+resid
//      6 f16 single+bias[m] | 7 f16 single
#define ROWB 80
#define COMPB (128 * ROWB)

template <int EPI, int MODE, bool F16>
__global__ __launch_bounds__(256, 1)
void mma_gemm(const bf16* __restrict__ Ah, const bf16* __restrict__ Al,
              const bf16* __restrict__ Bh, const bf16* __restrict__ Bl,
              float* __restrict__ Cf, void* __restrict__ Coh, void* __restrict__ Col,
              const float* __restrict__ bias, const float* __restrict__ resid,
              int K, int ldc,
              long long sA, long long sB, long long sC, long long sR)
{
    constexpr int NCOMP = (MODE == 0) ? 4 : (MODE == 1) ? 3 : 2;
    constexpr int BC    = (MODE == 0) ? 2 : (MODE == 1) ? 2 : 1;  // B-hi comp idx
    constexpr int BUFB = NCOMP * COMPB;
    extern __shared__ char sm[];
    const uint32_t sbase = (uint32_t)__cvta_generic_to_shared(sm);
    const int tid = threadIdx.x;
    const int lane = tid & 31;
    const int wid = tid >> 5;
    const int bm0 = blockIdx.y * 128;
    const int bn0 = blockIdx.x * 128;
    const int z = blockIdx.z;

    const bf16* gp[NCOMP];
    gp[0] = Ah + sA * z + (long long)bm0 * K;
    if (MODE == 0) {
        gp[1] = Al + sA * z + (long long)bm0 * K;
        gp[2] = Bh + sB * z + (long long)bn0 * K;
        gp[3] = Bl + sB * z + (long long)bn0 * K;
    } else if (MODE == 1) {
        gp[1] = Al + sA * z + (long long)bm0 * K;
        gp[2] = Bh + sB * z + (long long)bn0 * K;
    } else {
        gp[1] = Bh + sB * z + (long long)bn0 * K;
    }

    const int wm = (wid >> 1) * 32;
    const int wn = (wid & 1) * 64;

    float acc[2][8][4];
#pragma unroll
    for (int i = 0; i < 2; i++)
#pragma unroll
        for (int j = 0; j < 8; j++)
#pragma unroll
            for (int q = 0; q < 4; q++) acc[i][j][q] = 0.0f;

    auto load_chunk = [&](int k0, int buf) {
        const uint32_t b = sbase + buf * BUFB;
#pragma unroll
        for (int i = 0; i < NCOMP * 2; i++) {
            const int u = tid + i * 256;
            const int comp = u >> 9;
            const int rem = u & 511;
            const int row = rem >> 2;
            const int un = rem & 3;
            const bf16* g = gp[comp] + (long long)row * K + k0 + un * 8;
            const uint32_t s = b + comp * COMPB + row * ROWB + un * 16;
            CP_ASYNC16(s, g);
        }
        CP_COMMIT();
    };

    auto compute = [&](int buf) {
        const uint32_t b = sbase + buf * BUFB;
        const uint32_t arow = wm + (lane & 15);
        const uint32_t akoff = ((lane >> 4) & 1) * 16;
        const uint32_t brow = wn + ((lane >> 4) << 3) + (lane & 7);
        const uint32_t bkoff = ((lane >> 3) & 1) * 16;
#pragma unroll
        for (int s = 0; s < 2; s++) {
            uint32_t ah[2][4], al[2][4], bh[8][2], bl[8][2];
#pragma unroll
            for (int mt = 0; mt < 2; mt++) {
                const uint32_t addr = b + (arow + mt * 16) * ROWB + s * 32 + akoff;
                LDSM4(ah[mt], addr);
                if (MODE <= 1) LDSM4(al[mt], addr + COMPB);
            }
#pragma unroll
            for (int np = 0; np < 4; np++) {
                const uint32_t addr = b + BC * COMPB + (brow + np * 16) * ROWB
                                      + s * 32 + bkoff;
                uint32_t r[4];
                LDSM4(r, addr);
                bh[np*2][0] = r[0]; bh[np*2][1] = r[1];
                bh[np*2+1][0] = r[2]; bh[np*2+1][1] = r[3];
                if (MODE == 0) {
                    LDSM4(r, addr + COMPB);
                    bl[np*2][0] = r[0]; bl[np*2][1] = r[1];
                    bl[np*2+1][0] = r[2]; bl[np*2+1][1] = r[3];
                }
            }
#pragma unroll
            for (int mt = 0; mt < 2; mt++)
#pragma unroll
                for (int nt = 0; nt < 8; nt++) {
                    if (F16) {
                        MMA_F16(acc[mt][nt], ah[mt], bh[nt]);
                        if (MODE == 0) MMA_F16(acc[mt][nt], ah[mt], bl[nt]);
                        if (MODE <= 1) MMA_F16(acc[mt][nt], al[mt], bh[nt]);
                    } else {
                        MMA_BF16(acc[mt][nt], ah[mt], bh[nt]);
                        if (MODE == 0) MMA_BF16(acc[mt][nt], ah[mt], bl[nt]);
                        if (MODE <= 1) MMA_BF16(acc[mt][nt], al[mt], bh[nt]);
                    }
                }
        }
    };

    const int nch = K / 32;
    load_chunk(0, 0);
    int buf = 0;
    for (int c = 0; c < nch; c++) {
        CP_WAIT0();
        __syncthreads();
        if (c + 1 < nch) load_chunk((c + 1) * 32, buf ^ 1);
        compute(buf);
        buf ^= 1;
    }

    // ================= epilogue =================
    const int r0 = lane >> 2;
    const int cq = (lane & 3) * 2;
#pragma unroll
    for (int mt = 0; mt < 2; mt++) {
        const int mA = bm0 + wm + mt * 16 + r0;
        const int mB = mA + 8;
        float biasA = 0.0f, biasB = 0.0f;
        if (EPI == 3 || EPI == 6) { biasA = bias[mA]; biasB = bias[mB]; }
        const long long rowA = sC * z + (long long)mA * ldc;
        const long long rowB = sC * z + (long long)mB * ldc;
#pragma unroll
        for (int nt = 0; nt < 8; nt++) {
            const int n = bn0 + wn + nt * 8 + cq;
            float v0 = acc[mt][nt][0], v1 = acc[mt][nt][1];
            float v2 = acc[mt][nt][2], v3 = acc[mt][nt][3];
            if (EPI == 2) {
                const float bn0v = bias[n], bn1v = bias[n + 1];
                v0 += bn0v; v1 += bn1v; v2 += bn0v; v3 += bn1v;
            }
            if (EPI == 3 || EPI == 6) { v0 += biasA; v1 += biasA; v2 += biasB; v3 += biasB; }
            if (EPI == 0 || EPI == 3) {
                if (EPI == 3) {
                    const long long rA = sR * z + (long long)mA * ldc + n;
                    const long long rB = sR * z + (long long)mB * ldc + n;
                    float2 ra = *(const float2*)(resid + rA);
                    float2 rb = *(const float2*)(resid + rB);
                    v0 += ra.x; v1 += ra.y; v2 += rb.x; v3 += rb.y;
                }
                *(float2*)(Cf + rowA + n) = make_float2(v0, v1);
                *(float2*)(Cf + rowB + n) = make_float2(v2, v3);
            } else if (EPI == 6 || EPI == 7) {
                *(__half2*)((__half*)Coh + rowA + n) = __floats2half2_rn(v0, v1);
                *(__half2*)((__half*)Coh + rowB + n) = __floats2half2_rn(v2, v3);
            } else {
                __nv_bfloat162 hA = __floats2bfloat162_rn(v0, v1);
                __nv_bfloat162 hB = __floats2bfloat162_rn(v2, v3);
                __nv_bfloat162 lA = __floats2bfloat162_rn(
                    v0 - __bfloat162float(hA.x), v1 - __bfloat162float(hA.y));
                __nv_bfloat162 lB = __floats2bfloat162_rn(
                    v2 - __bfloat162float(hB.x), v3 - __bfloat162float(hB.y));
                *(__nv_bfloat162*)((bf16*)Coh + rowA + n) = hA;
                *(__nv_bfloat162*)((bf16*)Coh + rowB + n) = hB;
                *(__nv_bfloat162*)((bf16*)Col + rowA + n) = lA;
                *(__nv_bfloat162*)((bf16*)Col + rowB + n) = lB;
            }
        }
    }
}

// ================= pre-passes =================
__global__ __launch_bounds__(256)
void split_w_bf16(const float* __restrict__ s, bf16* __restrict__ h,
                  bf16* __restrict__ l, int n)
{
    int i = blockIdx.x * 256 + threadIdx.x;
    if (i < n) {
        float v = s[i];
        bf16 hi = __float2bfloat16(v);
        h[i] = hi;
        l[i] = __float2bfloat16(v - __bfloat162float(hi));
    }
}

__global__ __launch_bounds__(256)
void split_w_f16(const float* __restrict__ s, __half* __restrict__ h,
                 __half* __restrict__ l, int n)
{
    int i = blockIdx.x * 256 + threadIdx.x;
    if (i < n) {
        float v = s[i];
        __half hi = __float2half_rn(v);
        h[i] = hi;
        l[i] = __float2half_rn(v - __half2float(hi));
    }
}

__global__ __launch_bounds__(256)
void transpose_split_x(const float* __restrict__ x, bf16* __restrict__ th,
                       bf16* __restrict__ tl, __half* __restrict__ t16)
{
    __shared__ float tile[32][33];
    const int b = blockIdx.z;
    const int t0 = blockIdx.x * 32, c0 = blockIdx.y * 32;
    const int tx = threadIdx.x, ty = threadIdx.y;  // 32 x 8
    const float* xb = x + (long long)b * C_ * T_;
#pragma unroll
    for (int j = 0; j < 32; j += 8)
        tile[ty + j][tx] = xb[(long long)(c0 + ty + j) * T_ + t0 + tx];
    __syncthreads();
    bf16* thb = th + (long long)b * T_ * C_;
    bf16* tlb = tl + (long long)b * T_ * C_;
    __half* t16b = t16 + (long long)b * T_ * C_;
#pragma unroll
    for (int j = 0; j < 32; j += 8) {
        float v = tile[tx][ty + j];
        long long o = (long long)(t0 + ty + j) * C_ + c0 + tx;
        bf16 h = __float2bfloat16(v);
        thb[o] = h;
        tlb[o] = __float2bfloat16(v - __bfloat162float(h));
        t16b[o] = __float2half_rn(v);
    }
}

// ================= softmax (FFMA-poly exp, rows of f[b*T+t][s]) =============
__device__ __forceinline__ float fast_exp(float x)
{
    float y = x * 1.4426950408889634f;
    float t = y + 12582912.0f;
    int e = __float_as_int(t) - 0x4B400000;
    float r = t - 12582912.0f;
    float f = y - r;
    float pq = 1.5403530393381608e-4f;
    pq = fmaf(pq, f, 1.3333558146428443e-3f);
    pq = fmaf(pq, f, 9.618129107628477e-3f);
    pq = fmaf(pq, f, 5.550410866482158e-2f);
    pq = fmaf(pq, f, 2.402265069591007e-1f);
    pq = fmaf(pq, f, 6.931471805599453e-1f);
    pq = fmaf(pq, f, 1.0f);
    float res = __int_as_float(__float_as_int(pq) + (e << 23));
    return (y > -120.0f) ? res : 0.0f;
}

__global__ __launch_bounds__(256)
void softmax_f16(const float* __restrict__ f, __half* __restrict__ E)
{
    const long long base = (long long)blockIdx.x * T_;
    const int tid = threadIdx.x;
    const int lane = tid & 31, w = tid >> 5;
    __shared__ float red[8];

    float v[8];
    float mx = -1e30f;
#pragma unroll
    for (int i = 0; i < 8; i++) {
        v[i] = f[base + tid + i * 256];
        mx = fmaxf(mx, v[i]);
    }
#pragma unroll
    for (int o = 16; o; o >>= 1) mx = fmaxf(mx, __shfl_xor_sync(~0u, mx, o));
    if (lane == 0) red[w] = mx;
    __syncthreads();
    mx = red[0];
#pragma unroll
    for (int i = 1; i < 8; i++) mx = fmaxf(mx, red[i]);
    __syncthreads();

    float sum = 0.0f;
#pragma unroll
    for (int i = 0; i < 8; i++) {
        v[i] = fast_exp(v[i] - mx);
        sum += v[i];
    }
#pragma unroll
    for (int o = 16; o; o >>= 1) sum += __shfl_xor_sync(~0u, sum, o);
    if (lane == 0) red[w] = sum;
    __syncthreads();
    float tot = 0.0f;
#pragma unroll
    for (int i = 0; i < 8; i++) tot += red[i];
    const float inv = 1.0f / tot;

#pragma unroll
    for (int i = 0; i < 8; i++)
        E[base + tid + i * 256] = __float2half_rn(v[i] * inv);
}

// ================= batchnorm =================
__global__ __launch_bounds__(256)
void bn_stats(const float* __restrict__ s, float* __restrict__ mean, float* __restrict__ rstd)
{
    const int c = blockIdx.x;
    const int tid = threadIdx.x;
    float sum = 0.0f, sq = 0.0f;
    for (int idx = tid; idx < B_ * T_; idx += 256) {
        int b = idx >> 11;
        int t = idx & (T_ - 1);
        float v = s[(long long)b * C_ * T_ + (long long)c * T_ + t];
        sum += v;
        sq = fmaf(v, v, sq);
    }
    __shared__ float r1[256], r2[256];
    r1[tid] = sum; r2[tid] = sq;
    __syncthreads();
#pragma unroll
    for (int st = 128; st > 0; st >>= 1) {
        if (tid < st) { r1[tid] += r1[tid + st]; r2[tid] += r2[tid + st]; }
        __syncthreads();
    }
    if (tid == 0) {
        const float inv_n = 1.0f / (float)(B_ * T_);
        float m = r1[0] * inv_n;
        float var = r2[0] * inv_n - m * m;
        mean[c] = m;
        rstd[c] = rsqrtf(var + BN_EPS);
    }
}

__global__ __launch_bounds__(256)
void bn_apply(float* __restrict__ s, const float* __restrict__ mean,
              const float* __restrict__ rstd, const float* __restrict__ gamma,
              const float* __restrict__ beta)
{
    const int bc = blockIdx.x;
    const int c = bc & (C_ - 1);
    const long long base = (long long)bc * T_;
    const float m = mean[c], r = rstd[c], g = gamma[c], be = beta[c];
    for (int t = threadIdx.x; t < T_; t += 256)
        s[base + t] = fmaf((s[base + t] - m) * r, g, be);
}

// ================= launcher =================
extern "C" void kernel_launch(void* const* d_in, const int* in_sizes, int n_in,
                              void* d_out, int out_size)
{
    const float* x     = (const float*)d_in[0];
    const float* g_w   = (const float*)d_in[1];
    const float* g_b   = (const float*)d_in[2];
    const float* th_w  = (const float*)d_in[3];
    const float* th_b  = (const float*)d_in[4];
    const float* ph_w  = (const float*)d_in[5];
    const float* ph_b  = (const float*)d_in[6];
    const float* W_w   = (const float*)d_in[7];
    const float* W_b   = (const float*)d_in[8];
    const float* gamma = (const float*)d_in[9];
    const float* beta  = (const float*)d_in[10];
    float* out = (float*)d_out;

    bf16 *xTh, *xTl, *wth, *wtl, *wph, *wpl, *thh, *thl, *phh, *phl;
    __half *xT16, *wg16h, *wg16l, *W16h, *W16l, *g16, *E, *yT16;
    float *f, *mean, *rstd;
    cudaGetSymbolAddress((void**)&xTh, g_xTh);    cudaGetSymbolAddress((void**)&xTl, g_xTl);
    cudaGetSymbolAddress((void**)&xT16, g_xT16);
    cudaGetSymbolAddress((void**)&wg16h, g_wg16h); cudaGetSymbolAddress((void**)&wg16l, g_wg16l);
    cudaGetSymbolAddress((void**)&wth, g_wth);    cudaGetSymbolAddress((void**)&wtl, g_wtl);
    cudaGetSymbolAddress((void**)&wph, g_wph);    cudaGetSymbolAddress((void**)&wpl, g_wpl);
    cudaGetSymbolAddress((void**)&W16h, g_W16h);  cudaGetSymbolAddress((void**)&W16l, g_W16l);
    cudaGetSymbolAddress((void**)&g16, g_g16);
    cudaGetSymbolAddress((void**)&thh, g_thh);    cudaGetSymbolAddress((void**)&thl, g_thl);
    cudaGetSymbolAddress((void**)&phh, g_phh);    cudaGetSymbolAddress((void**)&phl, g_phl);
    cudaGetSymbolAddress((void**)&E, g_E);
    cudaGetSymbolAddress((void**)&yT16, g_yT16);
    cudaGetSymbolAddress((void**)&f, g_f);
    cudaGetSymbolAddress((void**)&mean, g_mean);  cudaGetSymbolAddress((void**)&rstd, g_rstd);

    const int SM_FULL3 = 2 * 4 * COMPB;   // 81920
    const int SM_AB2   = 2 * 3 * COMPB;   // 61440
    const int SM_SGL   = 2 * 2 * COMPB;   // 40960

    cudaFuncSetAttribute(mma_gemm<2,0,false>, cudaFuncAttributeMaxDynamicSharedMemorySize, SM_FULL3);
    cudaFuncSetAttribute(mma_gemm<0,0,false>, cudaFuncAttributeMaxDynamicSharedMemorySize, SM_FULL3);
    cudaFuncSetAttribute(mma_gemm<6,1,true>,  cudaFuncAttributeMaxDynamicSharedMemorySize, SM_AB2);
    cudaFuncSetAttribute(mma_gemm<3,1,true>,  cudaFuncAttributeMaxDynamicSharedMemorySize, SM_AB2);
    cudaFuncSetAttribute(mma_gemm<7,2,true>,  cudaFuncAttributeMaxDynamicSharedMemorySize, SM_SGL);

    const long long sXT = (long long)T_ * C_;
    const long long sX  = (long long)C_ * T_;
    const long long sTI = (long long)T_ * I_;
    const long long sIT = (long long)I_ * T_;
    const long long sF  = (long long)T_ * T_;

    dim3 blk(256);

    // 0) splits + transpose
    split_w_f16 <<<(I_ * C_ + 255) / 256, blk>>>(g_w,  wg16h, wg16l, I_ * C_);
    split_w_bf16<<<(I_ * C_ + 255) / 256, blk>>>(th_w, wth, wtl, I_ * C_);
    split_w_bf16<<<(I_ * C_ + 255) / 256, blk>>>(ph_w, wph, wpl, I_ * C_);
    split_w_f16 <<<(C_ * I_ + 255) / 256, blk>>>(W_w,  W16h, W16l, C_ * I_);
    transpose_split_x<<<dim3(T_ / 32, C_ / 32, B_), dim3(32, 8)>>>(x, xTh, xTl, xT16);

    // 1) g[i,t] = sum_c wg[i,c]*xT[t,c] + gb[i]  (M=I,N=T,K=C)  AB2 f16 -> f16
    mma_gemm<6,1,true><<<dim3(T_ / 128, I_ / 128, B_), blk, SM_AB2>>>(
        (const bf16*)wg16h, (const bf16*)wg16l, (const bf16*)xT16, nullptr,
        nullptr, g16, nullptr, g_b, nullptr, C_, T_, 0, sXT, sIT, 0);
    // 2) thT[t,i] = sum_c xT[t,c]*wth[i,c] + thb[i]  (M=T,N=I,K=C)  FULL3 bf16
    mma_gemm<2,0,false><<<dim3(I_ / 128, T_ / 128, B_), blk, SM_FULL3>>>(
        xTh, xTl, wth, wtl, nullptr, thh, thl, th_b, nullptr, C_, I_, sXT, 0, sTI, 0);
    // 3) phT[t,i]
    mma_gemm<2,0,false><<<dim3(I_ / 128, T_ / 128, B_), blk, SM_FULL3>>>(
        xTh, xTl, wph, wpl, nullptr, phh, phl, ph_b, nullptr, C_, I_, sXT, 0, sTI, 0);
    // 4) f[t,s] = sum_i thT[t,i]*phT[s,i]  (M=T,N=T,K=I)  FULL3 bf16 -> fp32
    mma_gemm<0,0,false><<<dim3(T_ / 128, T_ / 128, B_), blk, SM_FULL3>>>(
        thh, thl, phh, phl, f, nullptr, nullptr, nullptr, nullptr, I_, T_, sTI, sTI, sF, 0);
    // 5) softmax rows -> normalized fp16 E
    softmax_f16<<<B_ * T_, blk>>>(f, E);
    // 6) yT[t,i] = sum_s E[t,s]*g[i,s]  (M=T,N=I,K=T)  SINGLE f16 -> f16
    mma_gemm<7,2,true><<<dim3(I_ / 128, T_ / 128, B_), blk, SM_SGL>>>(
        (const bf16*)E, nullptr, (const bf16*)g16, nullptr,
        nullptr, yT16, nullptr, nullptr, nullptr, T_, I_, sF, sIT, sTI, 0);
    // 7) s[c,t] = sum_i W[c,i]*yT[t,i] + Wb[c] + x  (M=C,N=T,K=I)  AB2 f16 -> fp32
    mma_gemm<3,1,true><<<dim3(T_ / 128, C_ / 128, B_), blk, SM_AB2>>>(
        (const bf16*)W16h, (const bf16*)W16l, (const bf16*)yT16, nullptr,
        out, nullptr, nullptr, W_b, x, I_, T_, 0, sTI, sX, sX);

    // 8) batchnorm
    bn_stats<<<C_, blk>>>(out, mean, rstd);
    bn_apply<<<B_ * C_, blk>>>(out, mean, rstd, gamma, beta);
}

// round 8
// speedup vs baseline: 4.5931x; 1.1113x over previous
#include <cuda_runtime.h>
#include <cuda_bf16.h>
#include <cuda_fp16.h>
#include <math.h>
#include <stdint.h>

#define B_ 8
#define C_ 1024
#define T_ 2048
#define I_ 512
#define BN_EPS 1e-5f

typedef __nv_bfloat16 bf16;

// ================= static scratch =================
__device__ __align__(16) bf16   g_xTh[B_ * T_ * C_];
__device__ __align__(16) bf16   g_xTl[B_ * T_ * C_];
__device__ __align__(16) __half g_xT16[B_ * T_ * C_];
__device__ __align__(16) __half g_wg16[I_ * C_];
__device__ __align__(16) bf16   g_wth[I_ * C_],  g_wtl[I_ * C_];
__device__ __align__(16) bf16   g_wph[I_ * C_],  g_wpl[I_ * C_];
__device__ __align__(16) __half g_W16[C_ * I_];
__device__ __align__(16) __half g_g16[B_ * I_ * T_];
__device__ __align__(16) bf16   g_thh[B_ * T_ * I_], g_thl[B_ * T_ * I_];
__device__ __align__(16) bf16   g_phh[B_ * T_ * I_], g_phl[B_ * T_ * I_];
__device__ __align__(16) float  g_f[33554432];            // [B,T,S] fp32
__device__ __align__(16) __half g_E[33554432];            // fp16 attention
__device__ __align__(16) __half g_yT16[B_ * T_ * I_];
__device__ float g_mean[C_], g_rstd[C_];

// ================= PTX helpers (baseline features only) =================
#define LDSM4(r, a) \
    asm volatile("ldmatrix.sync.aligned.m8n8.x4.shared.b16 {%0,%1,%2,%3}, [%4];" \
        : "=r"((r)[0]), "=r"((r)[1]), "=r"((r)[2]), "=r"((r)[3]) : "r"(a))

#define MMA_BF16(c, a, b) \
    asm volatile("mma.sync.aligned.m16n8k16.row.col.f32.bf16.bf16.f32 " \
        "{%0,%1,%2,%3}, {%4,%5,%6,%7}, {%8,%9}, {%0,%1,%2,%3};" \
        : "+f"((c)[0]), "+f"((c)[1]), "+f"((c)[2]), "+f"((c)[3]) \
        : "r"((a)[0]), "r"((a)[1]), "r"((a)[2]), "r"((a)[3]), \
          "r"((b)[0]), "r"((b)[1]))

#define MMA_F16(c, a, b) \
    asm volatile("mma.sync.aligned.m16n8k16.row.col.f32.f16.f16.f32 " \
        "{%0,%1,%2,%3}, {%4,%5,%6,%7}, {%8,%9}, {%0,%1,%2,%3};" \
        : "+f"((c)[0]), "+f"((c)[1]), "+f"((c)[2]), "+f"((c)[3]) \
        : "r"((a)[0]), "r"((a)[1]), "r"((a)[2]), "r"((a)[3]), \
          "r"((b)[0]), "r"((b)[1]))

#define CP_ASYNC16(saddr, gptr) \
    asm volatile("cp.async.cg.shared.global [%0], [%1], 16;" \
        :: "r"(saddr), "l"(__cvta_generic_to_global(gptr)))
#define CP_COMMIT() asm volatile("cp.async.commit_group;" ::: "memory")
#define CP_WAIT0()  asm volatile("cp.async.wait_group 0;" ::: "memory")

// ================= split MMA GEMM: CTA tile 128x128, K-chunk 32 =============
// D[m,n] = sum_k A[m,k]*B[n,k].  K-major rows, 16-bit elements.
// MODE 0 (FULL3): comps [Ah,Al,Bh,Bl], products Ah*Bh + Ah*Bl + Al*Bh
// MODE 2 (SGL)  : comps [A,B],         product  A*B
// EPI: 0 fp32 | 2 bf16 split+bias[n] | 3 fp32+bias[m]+resid
//      6 f16 single+bias[m] | 7 f16 single
// DUAL: grid.z = 16; z>=8 selects second B/bias/output set (batch = z&7).
#define ROWB 80
#define COMPB (128 * ROWB)

template <int EPI, int MODE, bool F16, bool DUAL = false>
__global__ __launch_bounds__(256, 1)
void mma_gemm(const bf16* __restrict__ Ah, const bf16* __restrict__ Al,
              const bf16* __restrict__ Bh, const bf16* __restrict__ Bl,
              float* __restrict__ Cf, void* __restrict__ Coh, void* __restrict__ Col,
              const float* __restrict__ bias, const float* __restrict__ resid,
              int K, int ldc,
              long long sA, long long sB, long long sC, long long sR,
              const bf16* Bh2 = nullptr, const bf16* Bl2 = nullptr,
              const float* bias2 = nullptr, void* Coh2 = nullptr, void* Col2 = nullptr)
{
    constexpr int NCOMP = (MODE == 0) ? 4 : 2;
    constexpr int BC    = (MODE == 0) ? 2 : 1;  // B-hi comp idx
    constexpr int BUFB = NCOMP * COMPB;
    extern __shared__ char sm[];
    const uint32_t sbase = (uint32_t)__cvta_generic_to_shared(sm);
    const int tid = threadIdx.x;
    const int lane = tid & 31;
    const int wid = tid >> 5;
    const int bm0 = blockIdx.y * 128;
    const int bn0 = blockIdx.x * 128;

    const int zb = blockIdx.z;
    const int z = DUAL ? (zb & 7) : zb;
    if (DUAL && zb >= 8) {
        Bh = Bh2; Bl = Bl2; bias = bias2; Coh = Coh2; Col = Col2;
    }

    const bf16* gp[NCOMP];
    gp[0] = Ah + sA * z + (long long)bm0 * K;
    if (MODE == 0) {
        gp[1] = Al + sA * z + (long long)bm0 * K;
        gp[2] = Bh + sB * z + (long long)bn0 * K;
        gp[3] = Bl + sB * z + (long long)bn0 * K;
    } else {
        gp[1] = Bh + sB * z + (long long)bn0 * K;
    }

    const int wm = (wid >> 1) * 32;
    const int wn = (wid & 1) * 64;

    float acc[2][8][4];
#pragma unroll
    for (int i = 0; i < 2; i++)
#pragma unroll
        for (int j = 0; j < 8; j++)
#pragma unroll
            for (int q = 0; q < 4; q++) acc[i][j][q] = 0.0f;

    auto load_chunk = [&](int k0, int buf) {
        const uint32_t b = sbase + buf * BUFB;
#pragma unroll
        for (int i = 0; i < NCOMP * 2; i++) {
            const int u = tid + i * 256;
            const int comp = u >> 9;
            const int rem = u & 511;
            const int row = rem >> 2;
            const int un = rem & 3;
            const bf16* g = gp[comp] + (long long)row * K + k0 + un * 8;
            const uint32_t s = b + comp * COMPB + row * ROWB + un * 16;
            CP_ASYNC16(s, g);
        }
        CP_COMMIT();
    };

    auto compute = [&](int buf) {
        const uint32_t b = sbase + buf * BUFB;
        const uint32_t arow = wm + (lane & 15);
        const uint32_t akoff = ((lane >> 4) & 1) * 16;
        const uint32_t brow = wn + ((lane >> 4) << 3) + (lane & 7);
        const uint32_t bkoff = ((lane >> 3) & 1) * 16;
#pragma unroll
        for (int s = 0; s < 2; s++) {
            uint32_t ah[2][4], al[2][4], bh[8][2], bl[8][2];
#pragma unroll
            for (int mt = 0; mt < 2; mt++) {
                const uint32_t addr = b + (arow + mt * 16) * ROWB + s * 32 + akoff;
                LDSM4(ah[mt], addr);
                if (MODE == 0) LDSM4(al[mt], addr + COMPB);
            }
#pragma unroll
            for (int np = 0; np < 4; np++) {
                const uint32_t addr = b + BC * COMPB + (brow + np * 16) * ROWB
                                      + s * 32 + bkoff;
                uint32_t r[4];
                LDSM4(r, addr);
                bh[np*2][0] = r[0]; bh[np*2][1] = r[1];
                bh[np*2+1][0] = r[2]; bh[np*2+1][1] = r[3];
                if (MODE == 0) {
                    LDSM4(r, addr + COMPB);
                    bl[np*2][0] = r[0]; bl[np*2][1] = r[1];
                    bl[np*2+1][0] = r[2]; bl[np*2+1][1] = r[3];
                }
            }
#pragma unroll
            for (int mt = 0; mt < 2; mt++)
#pragma unroll
                for (int nt = 0; nt < 8; nt++) {
                    if (F16) {
                        MMA_F16(acc[mt][nt], ah[mt], bh[nt]);
                        if (MODE == 0) MMA_F16(acc[mt][nt], ah[mt], bl[nt]);
                        if (MODE == 0) MMA_F16(acc[mt][nt], al[mt], bh[nt]);
                    } else {
                        MMA_BF16(acc[mt][nt], ah[mt], bh[nt]);
                        if (MODE == 0) MMA_BF16(acc[mt][nt], ah[mt], bl[nt]);
                        if (MODE == 0) MMA_BF16(acc[mt][nt], al[mt], bh[nt]);
                    }
                }
        }
    };

    const int nch = K / 32;
    load_chunk(0, 0);
    int buf = 0;
    for (int c = 0; c < nch; c++) {
        CP_WAIT0();
        __syncthreads();
        if (c + 1 < nch) load_chunk((c + 1) * 32, buf ^ 1);
        compute(buf);
        buf ^= 1;
    }

    // ================= epilogue =================
    const int r0 = lane >> 2;
    const int cq = (lane & 3) * 2;
#pragma unroll
    for (int mt = 0; mt < 2; mt++) {
        const int mA = bm0 + wm + mt * 16 + r0;
        const int mB = mA + 8;
        float biasA = 0.0f, biasB = 0.0f;
        if (EPI == 3 || EPI == 6) { biasA = bias[mA]; biasB = bias[mB]; }
        const long long rowA = sC * z + (long long)mA * ldc;
        const long long rowB = sC * z + (long long)mB * ldc;
#pragma unroll
        for (int nt = 0; nt < 8; nt++) {
            const int n = bn0 + wn + nt * 8 + cq;
            float v0 = acc[mt][nt][0], v1 = acc[mt][nt][1];
            float v2 = acc[mt][nt][2], v3 = acc[mt][nt][3];
            if (EPI == 2) {
                const float bn0v = bias[n], bn1v = bias[n + 1];
                v0 += bn0v; v1 += bn1v; v2 += bn0v; v3 += bn1v;
            }
            if (EPI == 3 || EPI == 6) { v0 += biasA; v1 += biasA; v2 += biasB; v3 += biasB; }
            if (EPI == 0 || EPI == 3) {
                if (EPI == 3) {
                    const long long rA = sR * z + (long long)mA * ldc + n;
                    const long long rB = sR * z + (long long)mB * ldc + n;
                    float2 ra = *(const float2*)(resid + rA);
                    float2 rb = *(const float2*)(resid + rB);
                    v0 += ra.x; v1 += ra.y; v2 += rb.x; v3 += rb.y;
                }
                *(float2*)(Cf + rowA + n) = make_float2(v0, v1);
                *(float2*)(Cf + rowB + n) = make_float2(v2, v3);
            } else if (EPI == 6 || EPI == 7) {
                *(__half2*)((__half*)Coh + rowA + n) = __floats2half2_rn(v0, v1);
                *(__half2*)((__half*)Coh + rowB + n) = __floats2half2_rn(v2, v3);
            } else {
                __nv_bfloat162 hA = __floats2bfloat162_rn(v0, v1);
                __nv_bfloat162 hB = __floats2bfloat162_rn(v2, v3);
                __nv_bfloat162 lA = __floats2bfloat162_rn(
                    v0 - __bfloat162float(hA.x), v1 - __bfloat162float(hA.y));
                __nv_bfloat162 lB = __floats2bfloat162_rn(
                    v2 - __bfloat162float(hB.x), v3 - __bfloat162float(hB.y));
                *(__nv_bfloat162*)((bf16*)Coh + rowA + n) = hA;
                *(__nv_bfloat162*)((bf16*)Coh + rowB + n) = hB;
                *(__nv_bfloat162*)((bf16*)Col + rowA + n) = lA;
                *(__nv_bfloat162*)((bf16*)Col + rowB + n) = lB;
            }
        }
    }
}

// ================= weight prep: one launch, 4 tasks ==========================
// task 0: th_w -> bf16 split (wth, wtl)
// task 1: ph_w -> bf16 split (wph, wpl)
// task 2: g_w  -> fp16 single (wg16)
// task 3: W_w  -> fp16 single (W16)
__global__ __launch_bounds__(256)
void prep_weights(const float* __restrict__ th_w, const float* __restrict__ ph_w,
                  const float* __restrict__ gw,   const float* __restrict__ Ww,
                  bf16* __restrict__ wth, bf16* __restrict__ wtl,
                  bf16* __restrict__ wph, bf16* __restrict__ wpl,
                  __half* __restrict__ wg16, __half* __restrict__ W16)
{
    const int i = blockIdx.x * 256 + threadIdx.x;
    const int task = blockIdx.y;
    if (i >= I_ * C_) return;
    if (task == 0) {
        float v = th_w[i];
        bf16 h = __float2bfloat16(v);
        wth[i] = h;
        wtl[i] = __float2bfloat16(v - __bfloat162float(h));
    } else if (task == 1) {
        float v = ph_w[i];
        bf16 h = __float2bfloat16(v);
        wph[i] = h;
        wpl[i] = __float2bfloat16(v - __bfloat162float(h));
    } else if (task == 2) {
        wg16[i] = __float2half_rn(gw[i]);
    } else {
        W16[i] = __float2half_rn(Ww[i]);
    }
}

__global__ __launch_bounds__(256)
void transpose_split_x(const float* __restrict__ x, bf16* __restrict__ th,
                       bf16* __restrict__ tl, __half* __restrict__ t16)
{
    __shared__ float tile[32][33];
    const int b = blockIdx.z;
    const int t0 = blockIdx.x * 32, c0 = blockIdx.y * 32;
    const int tx = threadIdx.x, ty = threadIdx.y;  // 32 x 8
    const float* xb = x + (long long)b * C_ * T_;
#pragma unroll
    for (int j = 0; j < 32; j += 8)
        tile[ty + j][tx] = xb[(long long)(c0 + ty + j) * T_ + t0 + tx];
    __syncthreads();
    bf16* thb = th + (long long)b * T_ * C_;
    bf16* tlb = tl + (long long)b * T_ * C_;
    __half* t16b = t16 + (long long)b * T_ * C_;
#pragma unroll
    for (int j = 0; j < 32; j += 8) {
        float v = tile[tx][ty + j];
        long long o = (long long)(t0 + ty + j) * C_ + c0 + tx;
        bf16 h = __float2bfloat16(v);
        thb[o] = h;
        tlb[o] = __float2bfloat16(v - __bfloat162float(h));
        t16b[o] = __float2half_rn(v);
    }
}

// ================= softmax (FFMA-poly exp, rows of f[b*T+t][s]) =============
__device__ __forceinline__ float fast_exp(float x)
{
    float y = x * 1.4426950408889634f;
    float t = y + 12582912.0f;
    int e = __float_as_int(t) - 0x4B400000;
    float r = t - 12582912.0f;
    float f = y - r;
    float pq = 1.5403530393381608e-4f;
    pq = fmaf(pq, f, 1.3333558146428443e-3f);
    pq = fmaf(pq, f, 9.618129107628477e-3f);
    pq = fmaf(pq, f, 5.550410866482158e-2f);
    pq = fmaf(pq, f, 2.402265069591007e-1f);
    pq = fmaf(pq, f, 6.931471805599453e-1f);
    pq = fmaf(pq, f, 1.0f);
    float res = __int_as_float(__float_as_int(pq) + (e << 23));
    return (y > -120.0f) ? res : 0.0f;
}

__global__ __launch_bounds__(256)
void softmax_f16(const float* __restrict__ f, __half* __restrict__ E)
{
    const long long base = (long long)blockIdx.x * T_;
    const int tid = threadIdx.x;
    const int lane = tid & 31, w = tid >> 5;
    __shared__ float red[8];

    float v[8];
    float mx = -1e30f;
#pragma unroll
    for (int i = 0; i < 8; i++) {
        v[i] = f[base + tid + i * 256];
        mx = fmaxf(mx, v[i]);
    }
#pragma unroll
    for (int o = 16; o; o >>= 1) mx = fmaxf(mx, __shfl_xor_sync(~0u, mx, o));
    if (lane == 0) red[w] = mx;
    __syncthreads();
    mx = red[0];
#pragma unroll
    for (int i = 1; i < 8; i++) mx = fmaxf(mx, red[i]);
    __syncthreads();

    float sum = 0.0f;
#pragma unroll
    for (int i = 0; i < 8; i++) {
        v[i] = fast_exp(v[i] - mx);
        sum += v[i];
    }
#pragma unroll
    for (int o = 16; o; o >>= 1) sum += __shfl_xor_sync(~0u, sum, o);
    if (lane == 0) red[w] = sum;
    __syncthreads();
    float tot = 0.0f;
#pragma unroll
    for (int i = 0; i < 8; i++) tot += red[i];
    const float inv = 1.0f / tot;

#pragma unroll
    for (int i = 0; i < 8; i++)
        E[base + tid + i * 256] = __float2half_rn(v[i] * inv);
}

// ================= batchnorm =================
__global__ __launch_bounds__(256)
void bn_stats(const float* __restrict__ s, float* __restrict__ mean, float* __restrict__ rstd)
{
    const int c = blockIdx.x;
    const int tid = threadIdx.x;
    float sum = 0.0f, sq = 0.0f;
    for (int idx = tid; idx < B_ * T_; idx += 256) {
        int b = idx >> 11;
        int t = idx & (T_ - 1);
        float v = s[(long long)b * C_ * T_ + (long long)c * T_ + t];
        sum += v;
        sq = fmaf(v, v, sq);
    }
    __shared__ float r1[256], r2[256];
    r1[tid] = sum; r2[tid] = sq;
    __syncthreads();
#pragma unroll
    for (int st = 128; st > 0; st >>= 1) {
        if (tid < st) { r1[tid] += r1[tid + st]; r2[tid] += r2[tid + st]; }
        __syncthreads();
    }
    if (tid == 0) {
        const float inv_n = 1.0f / (float)(B_ * T_);
        float m = r1[0] * inv_n;
        float var = r2[0] * inv_n - m * m;
        mean[c] = m;
        rstd[c] = rsqrtf(var + BN_EPS);
    }
}

__global__ __launch_bounds__(256)
void bn_apply(float* __restrict__ s, const float* __restrict__ mean,
              const float* __restrict__ rstd, const float* __restrict__ gamma,
              const float* __restrict__ beta)
{
    const int bc = blockIdx.x;
    const int c = bc & (C_ - 1);
    const long long base = (long long)bc * T_;
    const float m = mean[c], r = rstd[c], g = gamma[c], be = beta[c];
    for (int t = threadIdx.x; t < T_; t += 256)
        s[base + t] = fmaf((s[base + t] - m) * r, g, be);
}

// ================= launcher =================
extern "C" void kernel_launch(void* const* d_in, const int* in_sizes, int n_in,
                              void* d_out, int out_size)
{
    const float* x     = (const float*)d_in[0];
    const float* g_w   = (const float*)d_in[1];
    const float* g_b   = (const float*)d_in[2];
    const float* th_w  = (const float*)d_in[3];
    const float* th_b  = (const float*)d_in[4];
    const float* ph_w  = (const float*)d_in[5];
    const float* ph_b  = (const float*)d_in[6];
    const float* W_w   = (const float*)d_in[7];
    const float* W_b   = (const float*)d_in[8];
    const float* gamma = (const float*)d_in[9];
    const float* beta  = (const float*)d_in[10];
    float* out = (float*)d_out;

    bf16 *xTh, *xTl, *wth, *wtl, *wph, *wpl, *thh, *thl, *phh, *phl;
    __half *xT16, *wg16, *W16, *g16, *E, *yT16;
    float *f, *mean, *rstd;
    cudaGetSymbolAddress((void**)&xTh, g_xTh);    cudaGetSymbolAddress((void**)&xTl, g_xTl);
    cudaGetSymbolAddress((void**)&xT16, g_xT16);
    cudaGetSymbolAddress((void**)&wg16, g_wg16);
    cudaGetSymbolAddress((void**)&wth, g_wth);    cudaGetSymbolAddress((void**)&wtl, g_wtl);
    cudaGetSymbolAddress((void**)&wph, g_wph);    cudaGetSymbolAddress((void**)&wpl, g_wpl);
    cudaGetSymbolAddress((void**)&W16, g_W16);
    cudaGetSymbolAddress((void**)&g16, g_g16);
    cudaGetSymbolAddress((void**)&thh, g_thh);    cudaGetSymbolAddress((void**)&thl, g_thl);
    cudaGetSymbolAddress((void**)&phh, g_phh);    cudaGetSymbolAddress((void**)&phl, g_phl);
    cudaGetSymbolAddress((void**)&E, g_E);
    cudaGetSymbolAddress((void**)&yT16, g_yT16);
    cudaGetSymbolAddress((void**)&f, g_f);
    cudaGetSymbolAddress((void**)&mean, g_mean);  cudaGetSymbolAddress((void**)&rstd, g_rstd);

    const int SM_FULL3 = 2 * 4 * COMPB;   // 81920
    const int SM_SGL   = 2 * 2 * COMPB;   // 40960

    cudaFuncSetAttribute((const void*)mma_gemm<2,0,false,true>,
                         cudaFuncAttributeMaxDynamicSharedMemorySize, SM_FULL3);
    cudaFuncSetAttribute((const void*)mma_gemm<0,0,false,false>,
                         cudaFuncAttributeMaxDynamicSharedMemorySize, SM_FULL3);
    cudaFuncSetAttribute((const void*)mma_gemm<6,2,true,false>,
                         cudaFuncAttributeMaxDynamicSharedMemorySize, SM_SGL);
    cudaFuncSetAttribute((const void*)mma_gemm<7,2,true,false>,
                         cudaFuncAttributeMaxDynamicSharedMemorySize, SM_SGL);
    cudaFuncSetAttribute((const void*)mma_gemm<3,2,true,false>,
                         cudaFuncAttributeMaxDynamicSharedMemorySize, SM_SGL);

    const long long sXT = (long long)T_ * C_;
    const long long sX  = (long long)C_ * T_;
    const long long sTI = (long long)T_ * I_;
    const long long sIT = (long long)I_ * T_;
    const long long sF  = (long long)T_ * T_;

    dim3 blk(256);

    // 0) weight prep (one launch) + x transpose/split
    prep_weights<<<dim3((I_ * C_ + 255) / 256, 4), blk>>>(
        th_w, ph_w, g_w, W_w, wth, wtl, wph, wpl, wg16, W16);
    transpose_split_x<<<dim3(T_ / 32, C_ / 32, B_), dim3(32, 8)>>>(x, xTh, xTl, xT16);

    // 1) g[i,t] = sum_c wg[i,c]*xT[t,c] + gb[i]  (M=I,N=T,K=C)  SGL f16
    mma_gemm<6,2,true,false><<<dim3(T_ / 128, I_ / 128, B_), blk, SM_SGL>>>(
        (const bf16*)wg16, nullptr, (const bf16*)xT16, nullptr,
        nullptr, g16, nullptr, g_b, nullptr, C_, T_, 0, sXT, sIT, 0);
    // 2+3) thT/phT[t,i] = sum_c xT[t,c]*w[i,c] + b[i]  (M=T,N=I,K=C)  FULL3 DUAL
    mma_gemm<2,0,false,true><<<dim3(I_ / 128, T_ / 128, 2 * B_), blk, SM_FULL3>>>(
        xTh, xTl, wth, wtl, nullptr, thh, thl, th_b, nullptr, C_, I_, sXT, 0, sTI, 0,
        wph, wpl, ph_b, phh, phl);
    // 4) f[t,s] = sum_i thT[t,i]*phT[s,i]  (M=T,N=T,K=I)  FULL3 -> fp32
    mma_gemm<0,0,false,false><<<dim3(T_ / 128, T_ / 128, B_), blk, SM_FULL3>>>(
        thh, thl, phh, phl, f, nullptr, nullptr, nullptr, nullptr, I_, T_, sTI, sTI, sF, 0);
    // 5) softmax rows -> normalized fp16 E
    softmax_f16<<<B_ * T_, blk>>>(f, E);
    // 6) yT[t,i] = sum_s E[t,s]*g[i,s]  (M=T,N=I,K=T)  SGL f16
    mma_gemm<7,2,true,false><<<dim3(I_ / 128, T_ / 128, B_), blk, SM_SGL>>>(
        (const bf16*)E, nullptr, (const bf16*)g16, nullptr,
        nullptr, yT16, nullptr, nullptr, nullptr, T_, I_, sF, sIT, sTI, 0);
    // 7) s[c,t] = sum_i W[c,i]*yT[t,i] + Wb[c] + x  (M=C,N=T,K=I)  SGL f16 -> fp32
    mma_gemm<3,2,true,false><<<dim3(T_ / 128, C_ / 128, B_), blk, SM_SGL>>>(
        (const bf16*)W16, nullptr, (const bf16*)yT16, nullptr,
        out, nullptr, nullptr, W_b, x, I_, T_, 0, sTI, sX, sX);

    // 8) batchnorm
    bn_stats<<<C_, blk>>>(out, mean, rstd);
    bn_apply<<<B_ * C_, blk>>>(out, mean, rstd, gamma, beta);
}

// round 9
// speedup vs baseline: 5.7109x; 1.2434x over previous
#include <cuda_runtime.h>
#include <cuda_bf16.h>
#include <cuda_fp16.h>
#include <math.h>
#include <stdint.h>

#define B_ 8
#define C_ 1024
#define T_ 2048
#define I_ 512
#define BN_EPS 1e-5f

typedef __nv_bfloat16 bf16;

// ================= static scratch =================
__device__ __align__(16) bf16   g_xTh[B_ * T_ * C_];
__device__ __align__(16) bf16   g_xTl[B_ * T_ * C_];
__device__ __align__(16) __half g_xT16[B_ * T_ * C_];
__device__ __align__(16) __half g_wg16[I_ * C_];
__device__ __align__(16) bf16   g_wth[I_ * C_],  g_wtl[I_ * C_];
__device__ __align__(16) bf16   g_wph[I_ * C_],  g_wpl[I_ * C_];
__device__ __align__(16) __half g_W16[C_ * I_];
__device__ __align__(16) __half g_g16[B_ * I_ * T_];
__device__ __align__(16) bf16   g_thh[B_ * T_ * I_], g_thl[B_ * T_ * I_];
__device__ __align__(16) bf16   g_phh[B_ * T_ * I_], g_phl[B_ * T_ * I_];
__device__ __align__(16) float  g_f[33554432];            // [B,T,S] fp32
__device__ __align__(16) __half g_E[33554432];            // fp16 attention
__device__ __align__(16) __half g_yT16[B_ * T_ * I_];
__device__ float g_mean[C_], g_rstd[C_];

// ================= PTX helpers (baseline features only) =================
#define LDSM4(r, a) \
    asm volatile("ldmatrix.sync.aligned.m8n8.x4.shared.b16 {%0,%1,%2,%3}, [%4];" \
        : "=r"((r)[0]), "=r"((r)[1]), "=r"((r)[2]), "=r"((r)[3]) : "r"(a))

#define MMA_BF16(c, a, b) \
    asm volatile("mma.sync.aligned.m16n8k16.row.col.f32.bf16.bf16.f32 " \
        "{%0,%1,%2,%3}, {%4,%5,%6,%7}, {%8,%9}, {%0,%1,%2,%3};" \
        : "+f"((c)[0]), "+f"((c)[1]), "+f"((c)[2]), "+f"((c)[3]) \
        : "r"((a)[0]), "r"((a)[1]), "r"((a)[2]), "r"((a)[3]), \
          "r"((b)[0]), "r"((b)[1]))

#define MMA_F16(c, a, b) \
    asm volatile("mma.sync.aligned.m16n8k16.row.col.f32.f16.f16.f32 " \
        "{%0,%1,%2,%3}, {%4,%5,%6,%7}, {%8,%9}, {%0,%1,%2,%3};" \
        : "+f"((c)[0]), "+f"((c)[1]), "+f"((c)[2]), "+f"((c)[3]) \
        : "r"((a)[0]), "r"((a)[1]), "r"((a)[2]), "r"((a)[3]), \
          "r"((b)[0]), "r"((b)[1]))

#define CP_ASYNC16(saddr, gptr) \
    asm volatile("cp.async.cg.shared.global [%0], [%1], 16;" \
        :: "r"(saddr), "l"(__cvta_generic_to_global(gptr)))
#define CP_COMMIT() asm volatile("cp.async.commit_group;" ::: "memory")
#define CP_WAIT0()  asm volatile("cp.async.wait_group 0;" ::: "memory")

// ================= split MMA GEMM: CTA tile 128x128, K-chunk 32 =============
// D[m,n] = sum_k A[m,k]*B[n,k].  K-major rows, 16-bit elements.
// MODE 0 (FULL3): comps [Ah,Al,Bh,Bl], products Ah*Bh + Ah*Bl + Al*Bh
// MODE 2 (SGL)  : comps [A,B],         product  A*B
// EPI: 0 fp32 | 2 bf16 split+bias[n] | 3 fp32+bias[m]+resid
//      6 f16 single+bias[m] | 7 f16 single
// DUAL: grid.z = 16; z>=8 selects second B/bias/output set (batch = z&7).
#define ROWB 80
#define COMPB (128 * ROWB)

template <int EPI, int MODE, bool F16, bool DUAL = false>
__global__ __launch_bounds__(256, 2)
void mma_gemm(const bf16* __restrict__ Ah, const bf16* __restrict__ Al,
              const bf16* __restrict__ Bh, const bf16* __restrict__ Bl,
              float* __restrict__ Cf, void* __restrict__ Coh, void* __restrict__ Col,
              const float* __restrict__ bias, const float* __restrict__ resid,
              int K, int ldc,
              long long sA, long long sB, long long sC, long long sR,
              const bf16* Bh2 = nullptr, const bf16* Bl2 = nullptr,
              const float* bias2 = nullptr, void* Coh2 = nullptr, void* Col2 = nullptr)
{
    constexpr int NCOMP = (MODE == 0) ? 4 : 2;
    constexpr int BC    = (MODE == 0) ? 2 : 1;  // B-hi comp idx
    constexpr int BUFB = NCOMP * COMPB;
    extern __shared__ char sm[];
    const uint32_t sbase = (uint32_t)__cvta_generic_to_shared(sm);
    const int tid = threadIdx.x;
    const int lane = tid & 31;
    const int wid = tid >> 5;
    const int bm0 = blockIdx.y * 128;
    const int bn0 = blockIdx.x * 128;

    const int zb = blockIdx.z;
    const int z = DUAL ? (zb & 7) : zb;
    if (DUAL && zb >= 8) {
        Bh = Bh2; Bl = Bl2; bias = bias2; Coh = Coh2; Col = Col2;
    }

    const bf16* gp[NCOMP];
    gp[0] = Ah + sA * z + (long long)bm0 * K;
    if (MODE == 0) {
        gp[1] = Al + sA * z + (long long)bm0 * K;
        gp[2] = Bh + sB * z + (long long)bn0 * K;
        gp[3] = Bl + sB * z + (long long)bn0 * K;
    } else {
        gp[1] = Bh + sB * z + (long long)bn0 * K;
    }

    const int wm = (wid >> 1) * 32;
    const int wn = (wid & 1) * 64;

    float acc[2][8][4];
#pragma unroll
    for (int i = 0; i < 2; i++)
#pragma unroll
        for (int j = 0; j < 8; j++)
#pragma unroll
            for (int q = 0; q < 4; q++) acc[i][j][q] = 0.0f;

    auto load_chunk = [&](int k0, int buf) {
        const uint32_t b = sbase + buf * BUFB;
#pragma unroll
        for (int i = 0; i < NCOMP * 2; i++) {
            const int u = tid + i * 256;
            const int comp = u >> 9;
            const int rem = u & 511;
            const int row = rem >> 2;
            const int un = rem & 3;
            const bf16* g = gp[comp] + (long long)row * K + k0 + un * 8;
            const uint32_t s = b + comp * COMPB + row * ROWB + un * 16;
            CP_ASYNC16(s, g);
        }
        CP_COMMIT();
    };

    // Register-lean compute: B fragments loaded per n16-group and consumed
    // immediately (keeps live set ~110 regs so 2 CTAs/SM fit).
    auto compute = [&](int buf) {
        const uint32_t b = sbase + buf * BUFB;
        const uint32_t arow = wm + (lane & 15);
        const uint32_t akoff = ((lane >> 4) & 1) * 16;
        const uint32_t brow = wn + ((lane >> 4) << 3) + (lane & 7);
        const uint32_t bkoff = ((lane >> 3) & 1) * 16;
#pragma unroll
        for (int s = 0; s < 2; s++) {
            uint32_t ah[2][4], al[2][4];
#pragma unroll
            for (int mt = 0; mt < 2; mt++) {
                const uint32_t addr = b + (arow + mt * 16) * ROWB + s * 32 + akoff;
                LDSM4(ah[mt], addr);
                if (MODE == 0) LDSM4(al[mt], addr + COMPB);
            }
#pragma unroll
            for (int np = 0; np < 4; np++) {
                const uint32_t addr = b + BC * COMPB + (brow + np * 16) * ROWB
                                      + s * 32 + bkoff;
                uint32_t rh[4], rl[4];
                LDSM4(rh, addr);
                if (MODE == 0) LDSM4(rl, addr + COMPB);
#pragma unroll
                for (int half = 0; half < 2; half++) {
                    const int nt = np * 2 + half;
                    uint32_t bhf[2] = { rh[half*2], rh[half*2+1] };
#pragma unroll
                    for (int mt = 0; mt < 2; mt++) {
                        if (F16) MMA_F16(acc[mt][nt], ah[mt], bhf);
                        else     MMA_BF16(acc[mt][nt], ah[mt], bhf);
                    }
                    if (MODE == 0) {
                        uint32_t blf[2] = { rl[half*2], rl[half*2+1] };
#pragma unroll
                        for (int mt = 0; mt < 2; mt++) {
                            MMA_BF16(acc[mt][nt], ah[mt], blf);
                            MMA_BF16(acc[mt][nt], al[mt], bhf);
                        }
                    }
                }
            }
        }
    };

    const int nch = K / 32;
    load_chunk(0, 0);
    int buf = 0;
    for (int c = 0; c < nch; c++) {
        CP_WAIT0();
        __syncthreads();
        if (c + 1 < nch) load_chunk((c + 1) * 32, buf ^ 1);
        compute(buf);
        buf ^= 1;
    }

    // ================= epilogue =================
    const int r0 = lane >> 2;
    const int cq = (lane & 3) * 2;
#pragma unroll
    for (int mt = 0; mt < 2; mt++) {
        const int mA = bm0 + wm + mt * 16 + r0;
        const int mB = mA + 8;
        float biasA = 0.0f, biasB = 0.0f;
        if (EPI == 3 || EPI == 6) { biasA = bias[mA]; biasB = bias[mB]; }
        const long long rowA = sC * z + (long long)mA * ldc;
        const long long rowB = sC * z + (long long)mB * ldc;
#pragma unroll
        for (int nt = 0; nt < 8; nt++) {
            const int n = bn0 + wn + nt * 8 + cq;
            float v0 = acc[mt][nt][0], v1 = acc[mt][nt][1];
            float v2 = acc[mt][nt][2], v3 = acc[mt][nt][3];
            if (EPI == 2) {
                const float bn0v = bias[n], bn1v = bias[n + 1];
                v0 += bn0v; v1 += bn1v; v2 += bn0v; v3 += bn1v;
            }
            if (EPI == 3 || EPI == 6) { v0 += biasA; v1 += biasA; v2 += biasB; v3 += biasB; }
            if (EPI == 0 || EPI == 3) {
                if (EPI == 3) {
                    const long long rA = sR * z + (long long)mA * ldc + n;
                    const long long rB = sR * z + (long long)mB * ldc + n;
                    float2 ra = *(const float2*)(resid + rA);
                    float2 rb = *(const float2*)(resid + rB);
                    v0 += ra.x; v1 += ra.y; v2 += rb.x; v3 += rb.y;
                }
                *(float2*)(Cf + rowA + n) = make_float2(v0, v1);
                *(float2*)(Cf + rowB + n) = make_float2(v2, v3);
            } else if (EPI == 6 || EPI == 7) {
                *(__half2*)((__half*)Coh + rowA + n) = __floats2half2_rn(v0, v1);
                *(__half2*)((__half*)Coh + rowB + n) = __floats2half2_rn(v2, v3);
            } else {
                __nv_bfloat162 hA = __floats2bfloat162_rn(v0, v1);
                __nv_bfloat162 hB = __floats2bfloat162_rn(v2, v3);
                __nv_bfloat162 lA = __floats2bfloat162_rn(
                    v0 - __bfloat162float(hA.x), v1 - __bfloat162float(hA.y));
                __nv_bfloat162 lB = __floats2bfloat162_rn(
                    v2 - __bfloat162float(hB.x), v3 - __bfloat162float(hB.y));
                *(__nv_bfloat162*)((bf16*)Coh + rowA + n) = hA;
                *(__nv_bfloat162*)((bf16*)Coh + rowB + n) = hB;
                *(__nv_bfloat162*)((bf16*)Col + rowA + n) = lA;
                *(__nv_bfloat162*)((bf16*)Col + rowB + n) = lB;
            }
        }
    }
}

// ================= weight prep: one launch, 4 tasks ==========================
__global__ __launch_bounds__(256)
void prep_weights(const float* __restrict__ th_w, const float* __restrict__ ph_w,
                  const float* __restrict__ gw,   const float* __restrict__ Ww,
                  bf16* __restrict__ wth, bf16* __restrict__ wtl,
                  bf16* __restrict__ wph, bf16* __restrict__ wpl,
                  __half* __restrict__ wg16, __half* __restrict__ W16)
{
    const int i = blockIdx.x * 256 + threadIdx.x;
    const int task = blockIdx.y;
    if (i >= I_ * C_) return;
    if (task == 0) {
        float v = th_w[i];
        bf16 h = __float2bfloat16(v);
        wth[i] = h;
        wtl[i] = __float2bfloat16(v - __bfloat162float(h));
    } else if (task == 1) {
        float v = ph_w[i];
        bf16 h = __float2bfloat16(v);
        wph[i] = h;
        wpl[i] = __float2bfloat16(v - __bfloat162float(h));
    } else if (task == 2) {
        wg16[i] = __float2half_rn(gw[i]);
    } else {
        W16[i] = __float2half_rn(Ww[i]);
    }
}

__global__ __launch_bounds__(256)
void transpose_split_x(const float* __restrict__ x, bf16* __restrict__ th,
                       bf16* __restrict__ tl, __half* __restrict__ t16)
{
    __shared__ float tile[32][33];
    const int b = blockIdx.z;
    const int t0 = blockIdx.x * 32, c0 = blockIdx.y * 32;
    const int tx = threadIdx.x, ty = threadIdx.y;  // 32 x 8
    const float* xb = x + (long long)b * C_ * T_;
#pragma unroll
    for (int j = 0; j < 32; j += 8)
        tile[ty + j][tx] = xb[(long long)(c0 + ty + j) * T_ + t0 + tx];
    __syncthreads();
    bf16* thb = th + (long long)b * T_ * C_;
    bf16* tlb = tl + (long long)b * T_ * C_;
    __half* t16b = t16 + (long long)b * T_ * C_;
#pragma unroll
    for (int j = 0; j < 32; j += 8) {
        float v = tile[tx][ty + j];
        long long o = (long long)(t0 + ty + j) * C_ + c0 + tx;
        bf16 h = __float2bfloat16(v);
        thb[o] = h;
        tlb[o] = __float2bfloat16(v - __bfloat162float(h));
        t16b[o] = __float2half_rn(v);
    }
}

// ================= softmax (FFMA-poly exp, rows of f[b*T+t][s]) =============
__device__ __forceinline__ float fast_exp(float x)
{
    float y = x * 1.4426950408889634f;
    float t = y + 12582912.0f;
    int e = __float_as_int(t) - 0x4B400000;
    float r = t - 12582912.0f;
    float f = y - r;
    float pq = 1.5403530393381608e-4f;
    pq = fmaf(pq, f, 1.3333558146428443e-3f);
    pq = fmaf(pq, f, 9.618129107628477e-3f);
    pq = fmaf(pq, f, 5.550410866482158e-2f);
    pq = fmaf(pq, f, 2.402265069591007e-1f);
    pq = fmaf(pq, f, 6.931471805599453e-1f);
    pq = fmaf(pq, f, 1.0f);
    float res = __int_as_float(__float_as_int(pq) + (e << 23));
    return (y > -120.0f) ? res : 0.0f;
}

__global__ __launch_bounds__(256)
void softmax_f16(const float* __restrict__ f, __half* __restrict__ E)
{
    const long long base = (long long)blockIdx.x * T_;
    const int tid = threadIdx.x;
    const int lane = tid & 31, w = tid >> 5;
    __shared__ float red[8];

    float v[8];
    float mx = -1e30f;
#pragma unroll
    for (int i = 0; i < 8; i++) {
        v[i] = f[base + tid + i * 256];
        mx = fmaxf(mx, v[i]);
    }
#pragma unroll
    for (int o = 16; o; o >>= 1) mx = fmaxf(mx, __shfl_xor_sync(~0u, mx, o));
    if (lane == 0) red[w] = mx;
    __syncthreads();
    mx = red[0];
#pragma unroll
    for (int i = 1; i < 8; i++) mx = fmaxf(mx, red[i]);
    __syncthreads();

    float sum = 0.0f;
#pragma unroll
    for (int i = 0; i < 8; i++) {
        v[i] = fast_exp(v[i] - mx);
        sum += v[i];
    }
#pragma unroll
    for (int o = 16; o; o >>= 1) sum += __shfl_xor_sync(~0u, sum, o);
    if (lane == 0) red[w] = sum;
    __syncthreads();
    float tot = 0.0f;
#pragma unroll
    for (int i = 0; i < 8; i++) tot += red[i];
    const float inv = 1.0f / tot;

#pragma unroll
    for (int i = 0; i < 8; i++)
        E[base + tid + i * 256] = __float2half_rn(v[i] * inv);
}

// ================= batchnorm =================
__global__ __launch_bounds__(256)
void bn_stats(const float* __restrict__ s, float* __restrict__ mean, float* __restrict__ rstd)
{
    const int c = blockIdx.x;
    const int tid = threadIdx.x;
    float sum = 0.0f, sq = 0.0f;
    for (int idx = tid; idx < B_ * T_; idx += 256) {
        int b = idx >> 11;
        int t = idx & (T_ - 1);
        float v = s[(long long)b * C_ * T_ + (long long)c * T_ + t];
        sum += v;
        sq = fmaf(v, v, sq);
    }
    __shared__ float r1[256], r2[256];
    r1[tid] = sum; r2[tid] = sq;
    __syncthreads();
#pragma unroll
    for (int st = 128; st > 0; st >>= 1) {
        if (tid < st) { r1[tid] += r1[tid + st]; r2[tid] += r2[tid + st]; }
        __syncthreads();
    }
    if (tid == 0) {
        const float inv_n = 1.0f / (float)(B_ * T_);
        float m = r1[0] * inv_n;
        float var = r2[0] * inv_n - m * m;
        mean[c] = m;
        rstd[c] = rsqrtf(var + BN_EPS);
    }
}

__global__ __launch_bounds__(256)
void bn_apply(float* __restrict__ s, const float* __restrict__ mean,
              const float* __restrict__ rstd, const float* __restrict__ gamma,
              const float* __restrict__ beta)
{
    const int bc = blockIdx.x;
    const int c = bc & (C_ - 1);
    const long long base = (long long)bc * T_;
    const float m = mean[c], r = rstd[c], g = gamma[c], be = beta[c];
    for (int t = threadIdx.x; t < T_; t += 256)
        s[base + t] = fmaf((s[base + t] - m) * r, g, be);
}

// ================= launcher =================
extern "C" void kernel_launch(void* const* d_in, const int* in_sizes, int n_in,
                              void* d_out, int out_size)
{
    const float* x     = (const float*)d_in[0];
    const float* g_w   = (const float*)d_in[1];
    const float* g_b   = (const float*)d_in[2];
    const float* th_w  = (const float*)d_in[3];
    const float* th_b  = (const float*)d_in[4];
    const float* ph_w  = (const float*)d_in[5];
    const float* ph_b  = (const float*)d_in[6];
    const float* W_w   = (const float*)d_in[7];
    const float* W_b   = (const float*)d_in[8];
    const float* gamma = (const float*)d_in[9];
    const float* beta  = (const float*)d_in[10];
    float* out = (float*)d_out;

    bf16 *xTh, *xTl, *wth, *wtl, *wph, *wpl, *thh, *thl, *phh, *phl;
    __half *xT16, *wg16, *W16, *g16, *E, *yT16;
    float *f, *mean, *rstd;
    cudaGetSymbolAddress((void**)&xTh, g_xTh);    cudaGetSymbolAddress((void**)&xTl, g_xTl);
    cudaGetSymbolAddress((void**)&xT16, g_xT16);
    cudaGetSymbolAddress((void**)&wg16, g_wg16);
    cudaGetSymbolAddress((void**)&wth, g_wth);    cudaGetSymbolAddress((void**)&wtl, g_wtl);
    cudaGetSymbolAddress((void**)&wph, g_wph);    cudaGetSymbolAddress((void**)&wpl, g_wpl);
    cudaGetSymbolAddress((void**)&W16, g_W16);
    cudaGetSymbolAddress((void**)&g16, g_g16);
    cudaGetSymbolAddress((void**)&thh, g_thh);    cudaGetSymbolAddress((void**)&thl, g_thl);
    cudaGetSymbolAddress((void**)&phh, g_phh);    cudaGetSymbolAddress((void**)&phl, g_phl);
    cudaGetSymbolAddress((void**)&E, g_E);
    cudaGetSymbolAddress((void**)&yT16, g_yT16);
    cudaGetSymbolAddress((void**)&f, g_f);
    cudaGetSymbolAddress((void**)&mean, g_mean);  cudaGetSymbolAddress((void**)&rstd, g_rstd);

    const int SM_FULL3 = 2 * 4 * COMPB;   // 81920
    const int SM_SGL   = 2 * 2 * COMPB;   // 40960

    cudaFuncSetAttribute((const void*)mma_gemm<2,0,false,true>,
                         cudaFuncAttributeMaxDynamicSharedMemorySize, SM_FULL3);
    cudaFuncSetAttribute((const void*)mma_gemm<0,0,false,false>,
                         cudaFuncAttributeMaxDynamicSharedMemorySize, SM_FULL3);
    cudaFuncSetAttribute((const void*)mma_gemm<6,2,true,false>,
                         cudaFuncAttributeMaxDynamicSharedMemorySize, SM_SGL);
    cudaFuncSetAttribute((const void*)mma_gemm<7,2,true,false>,
                         cudaFuncAttributeMaxDynamicSharedMemorySize, SM_SGL);
    cudaFuncSetAttribute((const void*)mma_gemm<3,2,true,false>,
                         cudaFuncAttributeMaxDynamicSharedMemorySize, SM_SGL);

    const long long sXT = (long long)T_ * C_;
    const long long sX  = (long long)C_ * T_;
    const long long sTI = (long long)T_ * I_;
    const long long sIT = (long long)I_ * T_;
    const long long sF  = (long long)T_ * T_;

    dim3 blk(256);

    // 0) weight prep (one launch) + x transpose/split
    prep_weights<<<dim3((I_ * C_ + 255) / 256, 4), blk>>>(
        th_w, ph_w, g_w, W_w, wth, wtl, wph, wpl, wg16, W16);
    transpose_split_x<<<dim3(T_ / 32, C_ / 32, B_), dim3(32, 8)>>>(x, xTh, xTl, xT16);

    // 1) g[i,t] = sum_c wg[i,c]*xT[t,c] + gb[i]  (M=I,N=T,K=C)  SGL f16
    mma_gemm<6,2,true,false><<<dim3(T_ / 128, I_ / 128, B_), blk, SM_SGL>>>(
        (const bf16*)wg16, nullptr, (const bf16*)xT16, nullptr,
        nullptr, g16, nullptr, g_b, nullptr, C_, T_, 0, sXT, sIT, 0);
    // 2+3) thT/phT[t,i] = sum_c xT[t,c]*w[i,c] + b[i]  (M=T,N=I,K=C)  FULL3 DUAL
    mma_gemm<2,0,false,true><<<dim3(I_ / 128, T_ / 128, 2 * B_), blk, SM_FULL3>>>(
        xTh, xTl, wth, wtl, nullptr, thh, thl, th_b, nullptr, C_, I_, sXT, 0, sTI, 0,
        wph, wpl, ph_b, phh, phl);
    // 4) f[t,s] = sum_i thT[t,i]*phT[s,i]  (M=T,N=T,K=I)  FULL3 -> fp32
    mma_gemm<0,0,false,false><<<dim3(T_ / 128, T_ / 128, B_), blk, SM_FULL3>>>(
        thh, thl, phh, phl, f, nullptr, nullptr, nullptr, nullptr, I_, T_, sTI, sTI, sF, 0);
    // 5) softmax rows -> normalized fp16 E
    softmax_f16<<<B_ * T_, blk>>>(f, E);
    // 6) yT[t,i] = sum_s E[t,s]*g[i,s]  (M=T,N=I,K=T)  SGL f16
    mma_gemm<7,2,true,false><<<dim3(I_ / 128, T_ / 128, B_), blk, SM_SGL>>>(
        (const bf16*)E, nullptr, (const bf16*)g16, nullptr,
        nullptr, yT16, nullptr, nullptr, nullptr, T_, I_, sF, sIT, sTI, 0);
    // 7) s[c,t] = sum_i W[c,i]*yT[t,i] + Wb[c] + x  (M=C,N=T,K=I)  SGL f16 -> fp32
    mma_gemm<3,2,true,false><<<dim3(T_ / 128, C_ / 128, B_), blk, SM_SGL>>>(
        (const bf16*)W16, nullptr, (const bf16*)yT16, nullptr,
        out, nullptr, nullptr, W_b, x, I_, T_, 0, sTI, sX, sX);

    // 8) batchnorm
    bn_stats<<<C_, blk>>>(out, mean, rstd);
    bn_apply<<<B_ * C_, blk>>>(out, mean, rstd, gamma, beta);
}

// round 10
// speedup vs baseline: 5.7884x; 1.0136x over previous
#include <cuda_runtime.h>
#include <cuda_bf16.h>
#include <cuda_fp16.h>
#include <math.h>
#include <stdint.h>

#define B_ 8
#define C_ 1024
#define T_ 2048
#define I_ 512
#define BN_EPS 1e-5f

typedef __nv_bfloat16 bf16;

// ================= static scratch =================
__device__ __align__(16) bf16   g_xTh[B_ * T_ * C_];
__device__ __align__(16) bf16   g_xTl[B_ * T_ * C_];
__device__ __align__(16) __half g_xT16[B_ * T_ * C_];
__device__ __align__(16) __half g_wg16[I_ * C_];
__device__ __align__(16) bf16   g_wth[I_ * C_],  g_wtl[I_ * C_];
__device__ __align__(16) bf16   g_wph[I_ * C_],  g_wpl[I_ * C_];
__device__ __align__(16) __half g_W16[C_ * I_];
__device__ __align__(16) __half g_g16[B_ * I_ * T_];
__device__ __align__(16) bf16   g_thh[B_ * T_ * I_], g_thl[B_ * T_ * I_];
__device__ __align__(16) bf16   g_phh[B_ * T_ * I_], g_phl[B_ * T_ * I_];
__device__ __align__(16) float  g_f[33554432];            // [B,T,S] fp32
__device__ __align__(16) __half g_E[33554432];            // fp16 attention
__device__ __align__(16) __half g_yT16[B_ * T_ * I_];
__device__ float g_mean[C_], g_rstd[C_];

// ================= PTX helpers (baseline features only) =================
#define LDSM4(r, a) \
    asm volatile("ldmatrix.sync.aligned.m8n8.x4.shared.b16 {%0,%1,%2,%3}, [%4];" \
        : "=r"((r)[0]), "=r"((r)[1]), "=r"((r)[2]), "=r"((r)[3]) : "r"(a))

#define MMA_BF16(c, a, b) \
    asm volatile("mma.sync.aligned.m16n8k16.row.col.f32.bf16.bf16.f32 " \
        "{%0,%1,%2,%3}, {%4,%5,%6,%7}, {%8,%9}, {%0,%1,%2,%3};" \
        : "+f"((c)[0]), "+f"((c)[1]), "+f"((c)[2]), "+f"((c)[3]) \
        : "r"((a)[0]), "r"((a)[1]), "r"((a)[2]), "r"((a)[3]), \
          "r"((b)[0]), "r"((b)[1]))

#define MMA_F16(c, a, b) \
    asm volatile("mma.sync.aligned.m16n8k16.row.col.f32.f16.f16.f32 " \
        "{%0,%1,%2,%3}, {%4,%5,%6,%7}, {%8,%9}, {%0,%1,%2,%3};" \
        : "+f"((c)[0]), "+f"((c)[1]), "+f"((c)[2]), "+f"((c)[3]) \
        : "r"((a)[0]), "r"((a)[1]), "r"((a)[2]), "r"((a)[3]), \
          "r"((b)[0]), "r"((b)[1]))

#define CP_ASYNC16(saddr, gptr) \
    asm volatile("cp.async.cg.shared.global [%0], [%1], 16;" \
        :: "r"(saddr), "l"(__cvta_generic_to_global(gptr)))
#define CP_COMMIT() asm volatile("cp.async.commit_group;" ::: "memory")

// ================= split MMA GEMM: CTA tile 128x128, K-chunk 32 =============
// D[m,n] = sum_k A[m,k]*B[n,k].  K-major rows, 16-bit elements.
// MODE 0 (FULL3): comps [Ah,Al,Bh,Bl], products Ah*Bh + Ah*Bl + Al*Bh, 2-stage
// MODE 2 (SGL)  : comps [A,B],         product  A*B,                   4-stage
// EPI: 0 fp32 | 2 bf16 split+bias[n] | 3 fp32+bias[m]+resid
//      6 f16 single+bias[m] | 7 f16 single
// DUAL: grid.z = 16; z>=8 selects second B/bias/output set (batch = z&7).
#define ROWB 80
#define COMPB (128 * ROWB)

template <int EPI, int MODE, bool F16, bool DUAL = false>
__global__ __launch_bounds__(256, 2)
void mma_gemm(const bf16* __restrict__ Ah, const bf16* __restrict__ Al,
              const bf16* __restrict__ Bh, const bf16* __restrict__ Bl,
              float* __restrict__ Cf, void* __restrict__ Coh, void* __restrict__ Col,
              const float* __restrict__ bias, const float* __restrict__ resid,
              int K, int ldc,
              long long sA, long long sB, long long sC, long long sR,
              const bf16* Bh2 = nullptr, const bf16* Bl2 = nullptr,
              const float* bias2 = nullptr, void* Coh2 = nullptr, void* Col2 = nullptr)
{
    constexpr int NCOMP  = (MODE == 0) ? 4 : 2;
    constexpr int BC     = (MODE == 0) ? 2 : 1;  // B-hi comp idx
    constexpr int NSTAGE = (MODE == 0) ? 2 : 4;
    constexpr int BUFB = NCOMP * COMPB;
    extern __shared__ char sm[];
    const uint32_t sbase = (uint32_t)__cvta_generic_to_shared(sm);
    const int tid = threadIdx.x;
    const int lane = tid & 31;
    const int wid = tid >> 5;
    const int bm0 = blockIdx.y * 128;
    const int bn0 = blockIdx.x * 128;

    const int zb = blockIdx.z;
    const int z = DUAL ? (zb & 7) : zb;
    if (DUAL && zb >= 8) {
        Bh = Bh2; Bl = Bl2; bias = bias2; Coh = Coh2; Col = Col2;
    }

    const bf16* gp[NCOMP];
    gp[0] = Ah + sA * z + (long long)bm0 * K;
    if (MODE == 0) {
        gp[1] = Al + sA * z + (long long)bm0 * K;
        gp[2] = Bh + sB * z + (long long)bn0 * K;
        gp[3] = Bl + sB * z + (long long)bn0 * K;
    } else {
        gp[1] = Bh + sB * z + (long long)bn0 * K;
    }

    const int wm = (wid >> 1) * 32;
    const int wn = (wid & 1) * 64;

    float acc[2][8][4];
#pragma unroll
    for (int i = 0; i < 2; i++)
#pragma unroll
        for (int j = 0; j < 8; j++)
#pragma unroll
            for (int q = 0; q < 4; q++) acc[i][j][q] = 0.0f;

    auto load_chunk = [&](int k0, int buf) {
        const uint32_t b = sbase + buf * BUFB;
#pragma unroll
        for (int i = 0; i < NCOMP * 2; i++) {
            const int u = tid + i * 256;
            const int comp = u >> 9;
            const int rem = u & 511;
            const int row = rem >> 2;
            const int un = rem & 3;
            const bf16* g = gp[comp] + (long long)row * K + k0 + un * 8;
            const uint32_t s = b + comp * COMPB + row * ROWB + un * 16;
            CP_ASYNC16(s, g);
        }
        CP_COMMIT();
    };

    // compute: product-major MMA order (same-acc gap >= 3) + B-frag prefetch
    auto compute = [&](int buf) {
        const uint32_t b = sbase + buf * BUFB;
        const uint32_t arow = wm + (lane & 15);
        const uint32_t akoff = ((lane >> 4) & 1) * 16;
        const uint32_t brow = wn + ((lane >> 4) << 3) + (lane & 7);
        const uint32_t bkoff = ((lane >> 3) & 1) * 16;
#pragma unroll
        for (int s = 0; s < 2; s++) {
            uint32_t ah[2][4], al[2][4];
#pragma unroll
            for (int mt = 0; mt < 2; mt++) {
                const uint32_t addr = b + (arow + mt * 16) * ROWB + s * 32 + akoff;
                LDSM4(ah[mt], addr);
                if (MODE == 0) LDSM4(al[mt], addr + COMPB);
            }
            const uint32_t bbase = b + BC * COMPB + brow * ROWB + s * 32 + bkoff;
            uint32_t rh[2][4], rl[2][4];
            LDSM4(rh[0], bbase);
            if (MODE == 0) LDSM4(rl[0], bbase + COMPB);
#pragma unroll
            for (int np = 0; np < 4; np++) {
                const int cur = np & 1;
                if (np < 3) {
                    const uint32_t na = bbase + (np + 1) * 16 * ROWB;
                    LDSM4(rh[cur ^ 1], na);
                    if (MODE == 0) LDSM4(rl[cur ^ 1], na + COMPB);
                }
                const int nb = np * 2;
                uint32_t b0[2] = { rh[cur][0], rh[cur][1] };
                uint32_t b1[2] = { rh[cur][2], rh[cur][3] };
                if (F16) {
                    MMA_F16(acc[0][nb],     ah[0], b0);
                    MMA_F16(acc[1][nb],     ah[1], b0);
                    MMA_F16(acc[0][nb + 1], ah[0], b1);
                    MMA_F16(acc[1][nb + 1], ah[1], b1);
                } else {
                    MMA_BF16(acc[0][nb],     ah[0], b0);
                    MMA_BF16(acc[1][nb],     ah[1], b0);
                    MMA_BF16(acc[0][nb + 1], ah[0], b1);
                    MMA_BF16(acc[1][nb + 1], ah[1], b1);
                }
                if (MODE == 0) {
                    uint32_t c0[2] = { rl[cur][0], rl[cur][1] };
                    uint32_t c1[2] = { rl[cur][2], rl[cur][3] };
                    MMA_BF16(acc[0][nb],     ah[0], c0);
                    MMA_BF16(acc[1][nb],     ah[1], c0);
                    MMA_BF16(acc[0][nb + 1], ah[0], c1);
                    MMA_BF16(acc[1][nb + 1], ah[1], c1);
                    MMA_BF16(acc[0][nb],     al[0], b0);
                    MMA_BF16(acc[1][nb],     al[1], b0);
                    MMA_BF16(acc[0][nb + 1], al[0], b1);
                    MMA_BF16(acc[1][nb + 1], al[1], b1);
                }
            }
        }
    };

    const int nch = K / 32;
    // prologue: fill NSTAGE-1 stages
#pragma unroll
    for (int p = 0; p < NSTAGE - 1; p++)
        load_chunk(p * 32, p);

    for (int c = 0; c < nch; c++) {
        asm volatile("cp.async.wait_group %0;" :: "n"(NSTAGE - 2) : "memory");
        __syncthreads();
        const int nxt = c + NSTAGE - 1;
        if (nxt < nch) load_chunk(nxt * 32, nxt % NSTAGE);
        compute(c % NSTAGE);
    }

    // ================= epilogue =================
    const int r0 = lane >> 2;
    const int cq = (lane & 3) * 2;
#pragma unroll
    for (int mt = 0; mt < 2; mt++) {
        const int mA = bm0 + wm + mt * 16 + r0;
        const int mB = mA + 8;
        float biasA = 0.0f, biasB = 0.0f;
        if (EPI == 3 || EPI == 6) { biasA = bias[mA]; biasB = bias[mB]; }
        const long long rowA = sC * z + (long long)mA * ldc;
        const long long rowB = sC * z + (long long)mB * ldc;
#pragma unroll
        for (int nt = 0; nt < 8; nt++) {
            const int n = bn0 + wn + nt * 8 + cq;
            float v0 = acc[mt][nt][0], v1 = acc[mt][nt][1];
            float v2 = acc[mt][nt][2], v3 = acc[mt][nt][3];
            if (EPI == 2) {
                const float bn0v = bias[n], bn1v = bias[n + 1];
                v0 += bn0v; v1 += bn1v; v2 += bn0v; v3 += bn1v;
            }
            if (EPI == 3 || EPI == 6) { v0 += biasA; v1 += biasA; v2 += biasB; v3 += biasB; }
            if (EPI == 0 || EPI == 3) {
                if (EPI == 3) {
                    const long long rA = sR * z + (long long)mA * ldc + n;
                    const long long rB = sR * z + (long long)mB * ldc + n;
                    float2 ra = *(const float2*)(resid + rA);
                    float2 rb = *(const float2*)(resid + rB);
                    v0 += ra.x; v1 += ra.y; v2 += rb.x; v3 += rb.y;
                }
                *(float2*)(Cf + rowA + n) = make_float2(v0, v1);
                *(float2*)(Cf + rowB + n) = make_float2(v2, v3);
            } else if (EPI == 6 || EPI == 7) {
                *(__half2*)((__half*)Coh + rowA + n) = __floats2half2_rn(v0, v1);
                *(__half2*)((__half*)Coh + rowB + n) = __floats2half2_rn(v2, v3);
            } else {
                __nv_bfloat162 hA = __floats2bfloat162_rn(v0, v1);
                __nv_bfloat162 hB = __floats2bfloat162_rn(v2, v3);
                __nv_bfloat162 lA = __floats2bfloat162_rn(
                    v0 - __bfloat162float(hA.x), v1 - __bfloat162float(hA.y));
                __nv_bfloat162 lB = __floats2bfloat162_rn(
                    v2 - __bfloat162float(hB.x), v3 - __bfloat162float(hB.y));
                *(__nv_bfloat162*)((bf16*)Coh + rowA + n) = hA;
                *(__nv_bfloat162*)((bf16*)Coh + rowB + n) = hB;
                *(__nv_bfloat162*)((bf16*)Col + rowA + n) = lA;
                *(__nv_bfloat162*)((bf16*)Col + rowB + n) = lB;
            }
        }
    }
}

// ================= weight prep: one launch, 4 tasks ==========================
__global__ __launch_bounds__(256)
void prep_weights(const float* __restrict__ th_w, const float* __restrict__ ph_w,
                  const float* __restrict__ gw,   const float* __restrict__ Ww,
                  bf16* __restrict__ wth, bf16* __restrict__ wtl,
                  bf16* __restrict__ wph, bf16* __restrict__ wpl,
                  __half* __restrict__ wg16, __half* __restrict__ W16)
{
    const int i = blockIdx.x * 256 + threadIdx.x;
    const int task = blockIdx.y;
    if (i >= I_ * C_) return;
    if (task == 0) {
        float v = th_w[i];
        bf16 h = __float2bfloat16(v);
        wth[i] = h;
        wtl[i] = __float2bfloat16(v - __bfloat162float(h));
    } else if (task == 1) {
        float v = ph_w[i];
        bf16 h = __float2bfloat16(v);
        wph[i] = h;
        wpl[i] = __float2bfloat16(v - __bfloat162float(h));
    } else if (task == 2) {
        wg16[i] = __float2half_rn(gw[i]);
    } else {
        W16[i] = __float2half_rn(Ww[i]);
    }
}

__global__ __launch_bounds__(256)
void transpose_split_x(const float* __restrict__ x, bf16* __restrict__ th,
                       bf16* __restrict__ tl, __half* __restrict__ t16)
{
    __shared__ float tile[32][33];
    const int b = blockIdx.z;
    const int t0 = blockIdx.x * 32, c0 = blockIdx.y * 32;
    const int tx = threadIdx.x, ty = threadIdx.y;  // 32 x 8
    const float* xb = x + (long long)b * C_ * T_;
#pragma unroll
    for (int j = 0; j < 32; j += 8)
        tile[ty + j][tx] = xb[(long long)(c0 + ty + j) * T_ + t0 + tx];
    __syncthreads();
    bf16* thb = th + (long long)b * T_ * C_;
    bf16* tlb = tl + (long long)b * T_ * C_;
    __half* t16b = t16 + (long long)b * T_ * C_;
#pragma unroll
    for (int j = 0; j < 32; j += 8) {
        float v = tile[tx][ty + j];
        long long o = (long long)(t0 + ty + j) * C_ + c0 + tx;
        bf16 h = __float2bfloat16(v);
        thb[o] = h;
        tlb[o] = __float2bfloat16(v - __bfloat162float(h));
        t16b[o] = __float2half_rn(v);
    }
}

// ================= softmax (FFMA-poly exp, rows of f[b*T+t][s]) =============
__device__ __forceinline__ float fast_exp(float x)
{
    float y = x * 1.4426950408889634f;
    float t = y + 12582912.0f;
    int e = __float_as_int(t) - 0x4B400000;
    float r = t - 12582912.0f;
    float f = y - r;
    float pq = 1.5403530393381608e-4f;
    pq = fmaf(pq, f, 1.3333558146428443e-3f);
    pq = fmaf(pq, f, 9.618129107628477e-3f);
    pq = fmaf(pq, f, 5.550410866482158e-2f);
    pq = fmaf(pq, f, 2.402265069591007e-1f);
    pq = fmaf(pq, f, 6.931471805599453e-1f);
    pq = fmaf(pq, f, 1.0f);
    float res = __int_as_float(__float_as_int(pq) + (e << 23));
    return (y > -120.0f) ? res : 0.0f;
}

__global__ __launch_bounds__(256)
void softmax_f16(const float* __restrict__ f, __half* __restrict__ E)
{
    const long long base = (long long)blockIdx.x * T_;
    const int tid = threadIdx.x;
    const int lane = tid & 31, w = tid >> 5;
    __shared__ float red[8];

    float v[8];
    float mx = -1e30f;
#pragma unroll
    for (int i = 0; i < 8; i++) {
        v[i] = f[base + tid + i * 256];
        mx = fmaxf(mx, v[i]);
    }
#pragma unroll
    for (int o = 16; o; o >>= 1) mx = fmaxf(mx, __shfl_xor_sync(~0u, mx, o));
    if (lane == 0) red[w] = mx;
    __syncthreads();
    mx = red[0];
#pragma unroll
    for (int i = 1; i < 8; i++) mx = fmaxf(mx, red[i]);
    __syncthreads();

    float sum = 0.0f;
#pragma unroll
    for (int i = 0; i < 8; i++) {
        v[i] = fast_exp(v[i] - mx);
        sum += v[i];
    }
#pragma unroll
    for (int o = 16; o; o >>= 1) sum += __shfl_xor_sync(~0u, sum, o);
    if (lane == 0) red[w] = sum;
    __syncthreads();
    float tot = 0.0f;
#pragma unroll
    for (int i = 0; i < 8; i++) tot += red[i];
    const float inv = 1.0f / tot;

#pragma unroll
    for (int i = 0; i < 8; i++)
        E[base + tid + i * 256] = __float2half_rn(v[i] * inv);
}

// ================= batchnorm =================
__global__ __launch_bounds__(256)
void bn_stats(const float* __restrict__ s, float* __restrict__ mean, float* __restrict__ rstd)
{
    const int c = blockIdx.x;
    const int tid = threadIdx.x;
    float sum = 0.0f, sq = 0.0f;
    for (int idx = tid; idx < B_ * T_; idx += 256) {
        int b = idx >> 11;
        int t = idx & (T_ - 1);
        float v = s[(long long)b * C_ * T_ + (long long)c * T_ + t];
        sum += v;
        sq = fmaf(v, v, sq);
    }
    __shared__ float r1[256], r2[256];
    r1[tid] = sum; r2[tid] = sq;
    __syncthreads();
#pragma unroll
    for (int st = 128; st > 0; st >>= 1) {
        if (tid < st) { r1[tid] += r1[tid + st]; r2[tid] += r2[tid + st]; }
        __syncthreads();
    }
    if (tid == 0) {
        const float inv_n = 1.0f / (float)(B_ * T_);
        float m = r1[0] * inv_n;
        float var = r2[0] * inv_n - m * m;
        mean[c] = m;
        rstd[c] = rsqrtf(var + BN_EPS);
    }
}

__global__ __launch_bounds__(256)
void bn_apply(float* __restrict__ s, const float* __restrict__ mean,
              const float* __restrict__ rstd, const float* __restrict__ gamma,
              const float* __restrict__ beta)
{
    const int bc = blockIdx.x;
    const int c = bc & (C_ - 1);
    const long long base = (long long)bc * T_;
    const float m = mean[c], r = rstd[c], g = gamma[c], be = beta[c];
    for (int t = threadIdx.x; t < T_; t += 256)
        s[base + t] = fmaf((s[base + t] - m) * r, g, be);
}

// ================= launcher =================
extern "C" void kernel_launch(void* const* d_in, const int* in_sizes, int n_in,
                              void* d_out, int out_size)
{
    const float* x     = (const float*)d_in[0];
    const float* g_w   = (const float*)d_in[1];
    const float* g_b   = (const float*)d_in[2];
    const float* th_w  = (const float*)d_in[3];
    const float* th_b  = (const float*)d_in[4];
    const float* ph_w  = (const float*)d_in[5];
    const float* ph_b  = (const float*)d_in[6];
    const float* W_w   = (const float*)d_in[7];
    const float* W_b   = (const float*)d_in[8];
    const float* gamma = (const float*)d_in[9];
    const float* beta  = (const float*)d_in[10];
    float* out = (float*)d_out;

    bf16 *xTh, *xTl, *wth, *wtl, *wph, *wpl, *thh, *thl, *phh, *phl;
    __half *xT16, *wg16, *W16, *g16, *E, *yT16;
    float *f, *mean, *rstd;
    cudaGetSymbolAddress((void**)&xTh, g_xTh);    cudaGetSymbolAddress((void**)&xTl, g_xTl);
    cudaGetSymbolAddress((void**)&xT16, g_xT16);
    cudaGetSymbolAddress((void**)&wg16, g_wg16);
    cudaGetSymbolAddress((void**)&wth, g_wth);    cudaGetSymbolAddress((void**)&wtl, g_wtl);
    cudaGetSymbolAddress((void**)&wph, g_wph);    cudaGetSymbolAddress((void**)&wpl, g_wpl);
    cudaGetSymbolAddress((void**)&W16, g_W16);
    cudaGetSymbolAddress((void**)&g16, g_g16);
    cudaGetSymbolAddress((void**)&thh, g_thh);    cudaGetSymbolAddress((void**)&thl, g_thl);
    cudaGetSymbolAddress((void**)&phh, g_phh);    cudaGetSymbolAddress((void**)&phl, g_phl);
    cudaGetSymbolAddress((void**)&E, g_E);
    cudaGetSymbolAddress((void**)&yT16, g_yT16);
    cudaGetSymbolAddress((void**)&f, g_f);
    cudaGetSymbolAddress((void**)&mean, g_mean);  cudaGetSymbolAddress((void**)&rstd, g_rstd);

    const int SM_FULL3 = 2 * 4 * COMPB;   // 81920 (2-stage x 4 comps)
    const int SM_SGL   = 4 * 2 * COMPB;   // 81920 (4-stage x 2 comps)

    cudaFuncSetAttribute((const void*)mma_gemm<2,0,false,true>,
                         cudaFuncAttributeMaxDynamicSharedMemorySize, SM_FULL3);
    cudaFuncSetAttribute((const void*)mma_gemm<0,0,false,false>,
                         cudaFuncAttributeMaxDynamicSharedMemorySize, SM_FULL3);
    cudaFuncSetAttribute((const void*)mma_gemm<6,2,true,false>,
                         cudaFuncAttributeMaxDynamicSharedMemorySize, SM_SGL);
    cudaFuncSetAttribute((const void*)mma_gemm<7,2,true,false>,
                         cudaFuncAttributeMaxDynamicSharedMemorySize, SM_SGL);
    cudaFuncSetAttribute((const void*)mma_gemm<3,2,true,false>,
                         cudaFuncAttributeMaxDynamicSharedMemorySize, SM_SGL);

    const long long sXT = (long long)T_ * C_;
    const long long sX  = (long long)C_ * T_;
    const long long sTI = (long long)T_ * I_;
    const long long sIT = (long long)I_ * T_;
    const long long sF  = (long long)T_ * T_;

    dim3 blk(256);

    // 0) weight prep (one launch) + x transpose/split
    prep_weights<<<dim3((I_ * C_ + 255) / 256, 4), blk>>>(
        th_w, ph_w, g_w, W_w, wth, wtl, wph, wpl, wg16, W16);
    transpose_split_x<<<dim3(T_ / 32, C_ / 32, B_), dim3(32, 8)>>>(x, xTh, xTl, xT16);

    // 1) g[i,t] = sum_c wg[i,c]*xT[t,c] + gb[i]  (M=I,N=T,K=C)  SGL f16
    mma_gemm<6,2,true,false><<<dim3(T_ / 128, I_ / 128, B_), blk, SM_SGL>>>(
        (const bf16*)wg16, nullptr, (const bf16*)xT16, nullptr,
        nullptr, g16, nullptr, g_b, nullptr, C_, T_, 0, sXT, sIT, 0);
    // 2+3) thT/phT[t,i] = sum_c xT[t,c]*w[i,c] + b[i]  (M=T,N=I,K=C)  FULL3 DUAL
    mma_gemm<2,0,false,true><<<dim3(I_ / 128, T_ / 128, 2 * B_), blk, SM_FULL3>>>(
        xTh, xTl, wth, wtl, nullptr, thh, thl, th_b, nullptr, C_, I_, sXT, 0, sTI, 0,
        wph, wpl, ph_b, phh, phl);
    // 4) f[t,s] = sum_i thT[t,i]*phT[s,i]  (M=T,N=T,K=I)  FULL3 -> fp32
    mma_gemm<0,0,false,false><<<dim3(T_ / 128, T_ / 128, B_), blk, SM_FULL3>>>(
        thh, thl, phh, phl, f, nullptr, nullptr, nullptr, nullptr, I_, T_, sTI, sTI, sF, 0);
    // 5) softmax rows -> normalized fp16 E
    softmax_f16<<<B_ * T_, blk>>>(f, E);
    // 6) yT[t,i] = sum_s E[t,s]*g[i,s]  (M=T,N=I,K=T)  SGL f16
    mma_gemm<7,2,true,false><<<dim3(I_ / 128, T_ / 128, B_), blk, SM_SGL>>>(
        (const bf16*)E, nullptr, (const bf16*)g16, nullptr,
        nullptr, yT16, nullptr, nullptr, nullptr, T_, I_, sF, sIT, sTI, 0);
    // 7) s[c,t] = sum_i W[c,i]*yT[t,i] + Wb[c] + x  (M=C,N=T,K=I)  SGL f16 -> fp32
    mma_gemm<3,2,true,false><<<dim3(T_ / 128, C_ / 128, B_), blk, SM_SGL>>>(
        (const bf16*)W16, nullptr, (const bf16*)yT16, nullptr,
        out, nullptr, nullptr, W_b, x, I_, T_, 0, sTI, sX, sX);

    // 8) batchnorm
    bn_stats<<<C_, blk>>>(out, mean, rstd);
    bn_apply<<<B_ * C_, blk>>>(out, mean, rstd, gamma, beta);
}